// round 12
// baseline (speedup 1.0000x reference)
#include <cuda_runtime.h>
#include <cuda_bf16.h>
#include <cuda_fp16.h>
#include <math.h>

#define B_ 8
#define T_ 1024
#define F_ 512
#define H_ 8
#define DK_ 64
#define P_ 2047

// -------- scratch (device globals; no allocations allowed) --------
__device__ float g_Q[(size_t)B_ * T_ * F_];                 // fp32 q proj
__device__ __half g_Kf[(size_t)B_ * T_ * F_];               // k fp16 (scores)
__device__ __nv_bfloat16 g_Vth[(size_t)B_ * H_ * DK_ * T_]; // v^T hi  [b,h,d,s]
__device__ __nv_bfloat16 g_Vtl[(size_t)B_ * H_ * DK_ * T_]; // v^T lo
__device__ __half g_Pf[(size_t)(P_ + 1) * F_];              // p fp16 (row 2047 spare=0)
__device__ float g_ctx[(size_t)B_ * T_ * F_];

// =====================================================================
// Helpers
// =====================================================================
__device__ __forceinline__ unsigned smem_u32(const void* p) {
    return (unsigned)__cvta_generic_to_shared(p);
}
__device__ __forceinline__ void ldsm_x4(unsigned addr, unsigned& r0, unsigned& r1,
                                        unsigned& r2, unsigned& r3) {
    asm volatile("ldmatrix.sync.aligned.m8n8.x4.shared.b16 {%0,%1,%2,%3}, [%4];"
                 : "=r"(r0), "=r"(r1), "=r"(r2), "=r"(r3) : "r"(addr));
}
__device__ __forceinline__ void ldsm_x2(unsigned addr, unsigned& r0, unsigned& r1) {
    asm volatile("ldmatrix.sync.aligned.m8n8.x2.shared.b16 {%0,%1}, [%2];"
                 : "=r"(r0), "=r"(r1) : "r"(addr));
}
__device__ __forceinline__ void mma_bf16(float& c0, float& c1, float& c2, float& c3,
                                         unsigned a0, unsigned a1, unsigned a2, unsigned a3,
                                         unsigned b0, unsigned b1) {
    asm volatile(
        "mma.sync.aligned.m16n8k16.row.col.f32.bf16.bf16.f32 "
        "{%0,%1,%2,%3},{%4,%5,%6,%7},{%8,%9},{%0,%1,%2,%3};"
        : "+f"(c0), "+f"(c1), "+f"(c2), "+f"(c3)
        : "r"(a0), "r"(a1), "r"(a2), "r"(a3), "r"(b0), "r"(b1));
}
__device__ __forceinline__ void mma_fp16(float& c0, float& c1, float& c2, float& c3,
                                         unsigned a0, unsigned a1, unsigned a2, unsigned a3,
                                         unsigned b0, unsigned b1) {
    asm volatile(
        "mma.sync.aligned.m16n8k16.row.col.f32.f16.f16.f32 "
        "{%0,%1,%2,%3},{%4,%5,%6,%7},{%8,%9},{%0,%1,%2,%3};"
        : "+f"(c0), "+f"(c1), "+f"(c2), "+f"(c3)
        : "r"(a0), "r"(a1), "r"(a2), "r"(a3), "r"(b0), "r"(b1));
}
__device__ __forceinline__ void split_hl(float x, __nv_bfloat16& h, __nv_bfloat16& l) {
    h = __float2bfloat16(x);
    l = __float2bfloat16(x - __bfloat162float(h));
}
__device__ __forceinline__ void pack_hl(float x0, float x1, unsigned& hi, unsigned& lo) {
    __nv_bfloat16 h0, l0, h1, l1;
    split_hl(x0, h0, l0);
    split_hl(x1, h1, l1);
    hi = ((unsigned)__bfloat16_as_ushort(h1) << 16) | (unsigned)__bfloat16_as_ushort(h0);
    lo = ((unsigned)__bfloat16_as_ushort(l1) << 16) | (unsigned)__bfloat16_as_ushort(l0);
}
__device__ __forceinline__ void cvt4(__nv_bfloat16* dh, __nv_bfloat16* dl, float4 v) {
    float f[4] = {v.x, v.y, v.z, v.w};
#pragma unroll
    for (int i = 0; i < 4; i++) split_hl(f[i], dh[i], dl[i]);
}
__device__ __forceinline__ void cvt4_f16(__nv_bfloat16* d, float4 v) {
    __half2 a = __floats2half2_rn(v.x, v.y);
    __half2 b = __floats2half2_rn(v.z, v.w);
    *(uint2*)d = make_uint2(*(unsigned*)&a, *(unsigned*)&b);
}
__device__ __forceinline__ void cp16(void* smem_dst, const void* gsrc) {
    unsigned d = smem_u32(smem_dst);
    asm volatile("cp.async.cg.shared.global [%0], [%1], 16;" :: "r"(d), "l"(gsrc));
}

// =====================================================================
// Tensor-core NT GEMM, multi-job batched over grid.z.
// prec 0: bf16x3 (3 MMAs). prec 1: single fp16 (1 MMA, hi planes only).
// mode 0: fp32 -> C. mode 1: fp16 -> (half*)Ch. mode 2: bf16 hi/lo V^T.
// =====================================================================
#define BK_ 32
#define LDSA (BK_ + 8)
#define GN_ 512
#define GK_ 512

struct GemmJob {
    const float* A; const float* W; const float* bias;
    float* C; __nv_bfloat16* Ch; __nv_bfloat16* Cl;
    int M; int mode; int prec;
};
struct GemmJobs { GemmJob j[4]; };

__global__ void __launch_bounds__(256) gemm_multi(GemmJobs jobs)
{
    __shared__ __nv_bfloat16 Ah[128][LDSA], Al[128][LDSA];
    __shared__ __nv_bfloat16 Wh[128][LDSA], Wl[128][LDSA];

    const GemmJob job = jobs.j[blockIdx.z];
    const int M = job.M;
    const int m0 = blockIdx.y * 128;
    if (m0 >= M) return;
    const int n0 = blockIdx.x * 128;
    const int prec = job.prec;

    const float* __restrict__ A = job.A;
    const float* __restrict__ W = job.W;

    const int tid = threadIdx.x;
    const int lane = tid & 31;
    const int warp = tid >> 5;
    const int wm = warp & 1;
    const int wn = warp >> 1;

    const int arow = lane & 15;
    const int asel = (lane >> 4) << 3;
    const int bn_off = lane & 7;
    const int bsel = ((lane >> 3) & 1) << 3;

    float acc[4][4][4];
#pragma unroll
    for (int i = 0; i < 4; i++)
#pragma unroll
        for (int j = 0; j < 4; j++)
#pragma unroll
            for (int q = 0; q < 4; q++) acc[i][j][q] = 0.f;

    for (int k0 = 0; k0 < GK_; k0 += BK_) {
#pragma unroll
        for (int q = 0; q < 4; q++) {
            int idx = tid + q * 256;
            int row = idx >> 3;
            int col = (idx & 7) << 2;
            int gm = m0 + row; if (gm >= M) gm = M - 1;
            float4 a4 = *(const float4*)(A + (size_t)gm * GK_ + k0 + col);
            int gn = n0 + row;
            float4 w4 = *(const float4*)(W + (size_t)gn * GK_ + k0 + col);
            if (prec) {
                cvt4_f16(&Ah[row][col], a4);
                cvt4_f16(&Wh[row][col], w4);
            } else {
                cvt4(&Ah[row][col], &Al[row][col], a4);
                cvt4(&Wh[row][col], &Wl[row][col], w4);
            }
        }
        __syncthreads();

        if (prec) {
            // single fp16: hi planes only, 1 MMA per fragment
#pragma unroll
            for (int kk = 0; kk < 2; kk++) {
                const int kb = kk << 4;
                unsigned ah[4][4], bh[4][2];
#pragma unroll
                for (int i = 0; i < 4; i++) {
                    int r = wm * 64 + i * 16 + arow;
                    ldsm_x4(smem_u32(&Ah[r][kb + asel]), ah[i][0], ah[i][1], ah[i][2], ah[i][3]);
                }
#pragma unroll
                for (int j = 0; j < 4; j++) {
                    int n = wn * 32 + j * 8 + bn_off;
                    ldsm_x2(smem_u32(&Wh[n][kb + bsel]), bh[j][0], bh[j][1]);
                }
#pragma unroll
                for (int i = 0; i < 4; i++)
#pragma unroll
                    for (int j = 0; j < 4; j++)
                        mma_fp16(acc[i][j][0], acc[i][j][1], acc[i][j][2], acc[i][j][3],
                                 ah[i][0], ah[i][1], ah[i][2], ah[i][3], bh[j][0], bh[j][1]);
            }
        } else {
#pragma unroll
            for (int kk = 0; kk < 2; kk++) {
                const int kb = kk << 4;
                unsigned ah[4][4], al[4][4], bh[4][2], bl[4][2];
#pragma unroll
                for (int i = 0; i < 4; i++) {
                    int r = wm * 64 + i * 16 + arow;
                    ldsm_x4(smem_u32(&Ah[r][kb + asel]), ah[i][0], ah[i][1], ah[i][2], ah[i][3]);
                    ldsm_x4(smem_u32(&Al[r][kb + asel]), al[i][0], al[i][1], al[i][2], al[i][3]);
                }
#pragma unroll
                for (int j = 0; j < 4; j++) {
                    int n = wn * 32 + j * 8 + bn_off;
                    ldsm_x2(smem_u32(&Wh[n][kb + bsel]), bh[j][0], bh[j][1]);
                    ldsm_x2(smem_u32(&Wl[n][kb + bsel]), bl[j][0], bl[j][1]);
                }
#pragma unroll
                for (int i = 0; i < 4; i++)
#pragma unroll
                    for (int j = 0; j < 4; j++) {
                        mma_bf16(acc[i][j][0], acc[i][j][1], acc[i][j][2], acc[i][j][3],
                                 ah[i][0], ah[i][1], ah[i][2], ah[i][3], bh[j][0], bh[j][1]);
                        mma_bf16(acc[i][j][0], acc[i][j][1], acc[i][j][2], acc[i][j][3],
                                 ah[i][0], ah[i][1], ah[i][2], ah[i][3], bl[j][0], bl[j][1]);
                        mma_bf16(acc[i][j][0], acc[i][j][1], acc[i][j][2], acc[i][j][3],
                                 al[i][0], al[i][1], al[i][2], al[i][3], bh[j][0], bh[j][1]);
                    }
            }
        }
        __syncthreads();
    }

#pragma unroll
    for (int i = 0; i < 4; i++) {
        int mbase = m0 + wm * 64 + i * 16 + (lane >> 2);
#pragma unroll
        for (int j = 0; j < 4; j++) {
            int n = n0 + wn * 32 + j * 8 + (lane & 3) * 2;
            float bb0 = job.bias ? job.bias[n] : 0.f;
            float bb1 = job.bias ? job.bias[n + 1] : 0.f;
#pragma unroll
            for (int half = 0; half < 2; half++) {
                int m = mbase + half * 8;
                if (m >= M) continue;
                float v0 = acc[i][j][half * 2 + 0] + bb0;
                float v1 = acc[i][j][half * 2 + 1] + bb1;
                if (job.mode == 0) {
                    job.C[(size_t)m * GN_ + n] = v0;
                    job.C[(size_t)m * GN_ + n + 1] = v1;
                } else if (job.mode == 1) {
                    __half2 hv = __floats2half2_rn(v0, v1);
                    *(__half2*)((__half*)job.Ch + (size_t)m * GN_ + n) = hv;
                } else {
                    int bb = m >> 10, ss = m & 1023;
#pragma unroll
                    for (int e = 0; e < 2; e++) {
                        int nn = n + e;
                        int hh = nn >> 6, dd = nn & 63;
                        size_t dst = (((size_t)(bb * H_ + hh) * DK_ + dd) * T_ + ss);
                        __nv_bfloat16 hv, lv;
                        split_hl(e ? v1 : v0, hv, lv);
                        job.Ch[dst] = hv; job.Cl[dst] = lv;
                    }
                }
            }
        }
    }
}

// =====================================================================
// Fused flash attention (unchanged from R11). Scores via single fp16
// MMAs; AV via bf16x3. cp.async pipelined, 8 warps, 128 t-rows/block.
// =====================================================================
#define FL_SMEM 137472

__global__ void __launch_bounds__(256) flash_kernel(
    const float* __restrict__ pu, const float* __restrict__ pv,
    const int* __restrict__ mask)
{
    extern __shared__ char sm[];
    __half* KF = (__half*)(sm);                           // 2 x [64][72]
    __nv_bfloat16* VH = (__nv_bfloat16*)(sm + 18432);     // 2 x [64 d][72 s]
    __nv_bfloat16* VL = (__nv_bfloat16*)(sm + 36864);
    __half* PF = (__half*)(sm + 55296);                   // [256][72] circular
    float* GS  = (float*)(sm + 92160);                    // [8 warps][16][88]
    float* MSK = (float*)(sm + 137216);                   // [64]
    __half* QUF = (__half*)(sm + 55296);                  // [128][72] (aliases)
    __half* QVF = (__half*)(sm + 73728);

    const int tid = threadIdx.x, lane = tid & 31, warp = tid >> 5;
    const int gid = lane >> 2, tig = lane & 3;
    const int bh = blockIdx.y, b = bh >> 3, h = bh & 7;
    const int t0 = blockIdx.x * 128;
    const int pbase0 = T_ - 1 - t0 - 127;

    for (int x = tid; x < 2048; x += 256) {
        int r = x >> 4, c = (x & 15) << 2;
        float4 q4 = *(const float4*)(g_Q + ((size_t)(b * T_ + t0 + r)) * F_ + h * DK_ + c);
        float4 u4 = *(const float4*)(pu + h * DK_ + c);
        float4 v4 = *(const float4*)(pv + h * DK_ + c);
        float qs[4] = {q4.x, q4.y, q4.z, q4.w};
        float us[4] = {u4.x, u4.y, u4.z, u4.w};
        float vs[4] = {v4.x, v4.y, v4.z, v4.w};
#pragma unroll
        for (int e = 0; e < 4; e++) {
            QUF[r * 72 + c + e] = __float2half((qs[e] + us[e]) * 0.125f);
            QVF[r * 72 + c + e] = __float2half((qs[e] + vs[e]) * 0.125f);
        }
    }
    __syncthreads();

    unsigned quf[4][4], qvf[4][4];
    {
        int ar = warp * 16 + (lane & 15);
        int ac = (lane >> 4) << 3;
#pragma unroll
        for (int kc = 0; kc < 4; kc++) {
            ldsm_x4(smem_u32(&QUF[ar * 72 + kc * 16 + ac]), quf[kc][0], quf[kc][1], quf[kc][2], quf[kc][3]);
            ldsm_x4(smem_u32(&QVF[ar * 72 + kc * 16 + ac]), qvf[kc][0], qvf[kc][1], qvf[kc][2], qvf[kc][3]);
        }
    }
    __syncthreads();

    for (int x = tid; x < 512; x += 256) {
        int r = x >> 3, c = (x & 7) << 3;
        size_t ksrc = ((size_t)(b * T_ + r)) * F_ + h * DK_ + c;
        cp16(&KF[r * 72 + c], g_Kf + ksrc);
        size_t vsrc = ((size_t)bh * DK_ + r) * T_ + c;
        cp16(&VH[r * 72 + c], g_Vth + vsrc);
        cp16(&VL[r * 72 + c], g_Vtl + vsrc);
    }
    for (int x = tid; x < 1536; x += 256) {
        int rr = x >> 3, c = (x & 7) << 3;
        int grow = pbase0 + rr; if (grow > P_) grow = P_;
        cp16(&PF[rr * 72 + c], g_Pf + (size_t)grow * F_ + h * DK_ + c);
    }
    asm volatile("cp.async.commit_group;");

    float o[8][4], oL[8][4];
#pragma unroll
    for (int nt = 0; nt < 8; nt++)
#pragma unroll
        for (int q = 0; q < 4; q++) { o[nt][q] = 0.f; oL[nt][q] = 0.f; }
    float mr0 = -1e30f, mr1 = -1e30f, l0 = 0.f, l1 = 0.f;
    float* GSw = GS + warp * (16 * 88);

    for (int i = 0; i < 16; i++) {
        const int s0 = i * 64;

        if (i < 15) {
            __half* kf = KF + ((i + 1) & 1) * 4608;
            __nv_bfloat16* vh = VH + ((i + 1) & 1) * 4608;
            __nv_bfloat16* vl = VL + ((i + 1) & 1) * 4608;
            int s0n = s0 + 64;
            for (int x = tid; x < 512; x += 256) {
                int r = x >> 3, c = (x & 7) << 3;
                size_t ksrc = ((size_t)(b * T_ + s0n + r)) * F_ + h * DK_ + c;
                cp16(&kf[r * 72 + c], g_Kf + ksrc);
                size_t vsrc = ((size_t)bh * DK_ + r) * T_ + s0n + c;
                cp16(&vh[r * 72 + c], g_Vth + vsrc);
                cp16(&vl[r * 72 + c], g_Vtl + vsrc);
            }
            int u0 = 192 + 64 * i;
            for (int x = tid; x < 512; x += 256) {
                int rr = x >> 3, c = (x & 7) << 3;
                int un = u0 + rr;
                int slot = un & 255;
                int grow = pbase0 + un; if (grow > P_) grow = P_;
                cp16(&PF[slot * 72 + c], g_Pf + (size_t)grow * F_ + h * DK_ + c);
            }
            asm volatile("cp.async.commit_group;");
        }
        if (tid < 64) MSK[tid] = (mask[b * T_ + s0 + tid] == 0) ? -3.0e38f : 0.f;
        if (i < 15) asm volatile("cp.async.wait_group 1;" ::: "memory");
        else        asm volatile("cp.async.wait_group 0;" ::: "memory");
        __syncthreads();

        const __half* kf = KF + (i & 1) * 4608;
        const __nv_bfloat16* vh = VH + (i & 1) * 4608;
        const __nv_bfloat16* vl = VL + (i & 1) * 4608;
        const int off = (64 * i) & 255;

        {
            int prow = 112 - 16 * warp + (lane & 7);
            int psel = ((lane >> 3) & 1) << 3;
#pragma unroll
            for (int nt = 0; nt < 10; nt++) {
                float gA0 = 0.f, gA1 = 0.f, gA2 = 0.f, gA3 = 0.f;
                float gB0 = 0.f, gB1 = 0.f, gB2 = 0.f, gB3 = 0.f;
                int prw = (prow + nt * 8 + off) & 255;
#pragma unroll
                for (int kc = 0; kc < 4; kc += 2) {
                    unsigned p0, p1, p2, p3;
                    ldsm_x2(smem_u32(&PF[prw * 72 + kc * 16 + psel]), p0, p1);
                    ldsm_x2(smem_u32(&PF[prw * 72 + (kc + 1) * 16 + psel]), p2, p3);
                    mma_fp16(gA0, gA1, gA2, gA3, qvf[kc][0], qvf[kc][1], qvf[kc][2], qvf[kc][3], p0, p1);
                    mma_fp16(gB0, gB1, gB2, gB3, qvf[kc + 1][0], qvf[kc + 1][1], qvf[kc + 1][2], qvf[kc + 1][3], p2, p3);
                }
                int gc = nt * 8 + 2 * tig;
                GSw[gid * 88 + gc] = gA0 + gB0;
                GSw[gid * 88 + gc + 1] = gA1 + gB1;
                GSw[(gid + 8) * 88 + gc] = gA2 + gB2;
                GSw[(gid + 8) * 88 + gc + 1] = gA3 + gB3;
            }
        }
        __syncwarp();

        float sf[8][4];
        {
            int krow = lane & 7;
            int ksel = ((lane >> 3) & 1) << 3;
#pragma unroll
            for (int nt = 0; nt < 8; nt++) {
                float aA0 = 0.f, aA1 = 0.f, aA2 = 0.f, aA3 = 0.f;
                float aB0 = 0.f, aB1 = 0.f, aB2 = 0.f, aB3 = 0.f;
#pragma unroll
                for (int kc = 0; kc < 4; kc += 2) {
                    unsigned k0, k1, k2, k3;
                    ldsm_x2(smem_u32(&kf[(nt * 8 + krow) * 72 + kc * 16 + ksel]), k0, k1);
                    ldsm_x2(smem_u32(&kf[(nt * 8 + krow) * 72 + (kc + 1) * 16 + ksel]), k2, k3);
                    mma_fp16(aA0, aA1, aA2, aA3, quf[kc][0], quf[kc][1], quf[kc][2], quf[kc][3], k0, k1);
                    mma_fp16(aB0, aB1, aB2, aB3, quf[kc + 1][0], quf[kc + 1][1], quf[kc + 1][2], quf[kc + 1][3], k2, k3);
                }
                int col = nt * 8 + 2 * tig;
                sf[nt][0] = aA0 + aB0 + GSw[gid * 88 + col - gid + 15] + MSK[col];
                sf[nt][1] = aA1 + aB1 + GSw[gid * 88 + col - gid + 16] + MSK[col + 1];
                sf[nt][2] = aA2 + aB2 + GSw[(gid + 8) * 88 + col - gid + 7] + MSK[col];
                sf[nt][3] = aA3 + aB3 + GSw[(gid + 8) * 88 + col - gid + 8] + MSK[col + 1];
            }
        }

        float mx0 = -1e30f, mx1 = -1e30f;
#pragma unroll
        for (int nt = 0; nt < 8; nt++) {
            mx0 = fmaxf(mx0, fmaxf(sf[nt][0], sf[nt][1]));
            mx1 = fmaxf(mx1, fmaxf(sf[nt][2], sf[nt][3]));
        }
        mx0 = fmaxf(mx0, __shfl_xor_sync(0xffffffffu, mx0, 1));
        mx0 = fmaxf(mx0, __shfl_xor_sync(0xffffffffu, mx0, 2));
        mx1 = fmaxf(mx1, __shfl_xor_sync(0xffffffffu, mx1, 1));
        mx1 = fmaxf(mx1, __shfl_xor_sync(0xffffffffu, mx1, 2));
        float mn0 = fmaxf(mr0, mx0), mn1 = fmaxf(mr1, mx1);
        float sc0 = __expf(mr0 - mn0), sc1 = __expf(mr1 - mn1);
        float su0 = 0.f, su1 = 0.f;
#pragma unroll
        for (int nt = 0; nt < 8; nt++) {
            sf[nt][0] = __expf(sf[nt][0] - mn0);
            sf[nt][1] = __expf(sf[nt][1] - mn0);
            sf[nt][2] = __expf(sf[nt][2] - mn1);
            sf[nt][3] = __expf(sf[nt][3] - mn1);
            su0 += sf[nt][0] + sf[nt][1];
            su1 += sf[nt][2] + sf[nt][3];
        }
        su0 += __shfl_xor_sync(0xffffffffu, su0, 1);
        su0 += __shfl_xor_sync(0xffffffffu, su0, 2);
        su1 += __shfl_xor_sync(0xffffffffu, su1, 1);
        su1 += __shfl_xor_sync(0xffffffffu, su1, 2);
        l0 = l0 * sc0 + su0;
        l1 = l1 * sc1 + su1;
        mr0 = mn0; mr1 = mn1;
#pragma unroll
        for (int nt = 0; nt < 8; nt++) {
            o[nt][0] *= sc0;  o[nt][1] *= sc0;
            o[nt][2] *= sc1;  o[nt][3] *= sc1;
            oL[nt][0] *= sc0; oL[nt][1] *= sc0;
            oL[nt][2] *= sc1; oL[nt][3] *= sc1;
        }

        {
            int vrow = lane & 7;
            int vsel = ((lane >> 3) & 1) << 3;
#pragma unroll
            for (int kc = 0; kc < 4; kc++) {
                unsigned ah[4], al[4];
                pack_hl(sf[2 * kc][0], sf[2 * kc][1], ah[0], al[0]);
                pack_hl(sf[2 * kc][2], sf[2 * kc][3], ah[1], al[1]);
                pack_hl(sf[2 * kc + 1][0], sf[2 * kc + 1][1], ah[2], al[2]);
                pack_hl(sf[2 * kc + 1][2], sf[2 * kc + 1][3], ah[3], al[3]);
#pragma unroll
                for (int nt = 0; nt < 8; nt++) {
                    unsigned v0, v1, w0, w1;
                    ldsm_x2(smem_u32(&vh[(nt * 8 + vrow) * 72 + kc * 16 + vsel]), v0, v1);
                    ldsm_x2(smem_u32(&vl[(nt * 8 + vrow) * 72 + kc * 16 + vsel]), w0, w1);
                    mma_bf16(o[nt][0], o[nt][1], o[nt][2], o[nt][3],
                             ah[0], ah[1], ah[2], ah[3], v0, v1);
                    mma_bf16(oL[nt][0], oL[nt][1], oL[nt][2], oL[nt][3],
                             ah[0], ah[1], ah[2], ah[3], w0, w1);
                    mma_bf16(oL[nt][0], oL[nt][1], oL[nt][2], oL[nt][3],
                             al[0], al[1], al[2], al[3], v0, v1);
                }
            }
        }
        __syncthreads();
    }

    float inv0 = (l0 > 0.f) ? 1.f / l0 : 0.f;
    float inv1 = (l1 > 0.f) ? 1.f / l1 : 0.f;
    int row0 = t0 + warp * 16 + gid;
#pragma unroll
    for (int nt = 0; nt < 8; nt++) {
        int colg = h * DK_ + nt * 8 + 2 * tig;
        float2 w0 = make_float2((o[nt][0] + oL[nt][0]) * inv0, (o[nt][1] + oL[nt][1]) * inv0);
        *(float2*)&g_ctx[((size_t)(b * T_ + row0)) * F_ + colg] = w0;
        float2 w1 = make_float2((o[nt][2] + oL[nt][2]) * inv1, (o[nt][3] + oL[nt][3]) * inv1);
        *(float2*)&g_ctx[((size_t)(b * T_ + row0 + 8)) * F_ + colg] = w1;
    }
}

// =====================================================================
extern "C" void kernel_launch(void* const* d_in, const int* in_sizes, int n_in,
                              void* d_out, int out_size)
{
    const float* query   = (const float*)d_in[0];
    const float* key_in  = (const float*)d_in[1];
    const float* value   = (const float*)d_in[2];
    const float* pos_emb = (const float*)d_in[3];
    const int*   mask    = (const int*)d_in[4];
    const float* Wq = (const float*)d_in[5];
    const float* bq = (const float*)d_in[6];
    const float* Wk = (const float*)d_in[7];
    const float* bk = (const float*)d_in[8];
    const float* Wv = (const float*)d_in[9];
    const float* bv = (const float*)d_in[10];
    const float* Wo = (const float*)d_in[11];
    const float* bo = (const float*)d_in[12];
    const float* Wp = (const float*)d_in[13];
    const float* pu = (const float*)d_in[14];
    const float* pv = (const float*)d_in[15];
    float* out = (float*)d_out;

    float *Qp, *Cp;
    __half *Kfp, *Pfp;
    __nv_bfloat16 *Vthp, *Vtlp;
    cudaGetSymbolAddress((void**)&Qp,   g_Q);
    cudaGetSymbolAddress((void**)&Cp,   g_ctx);
    cudaGetSymbolAddress((void**)&Kfp,  g_Kf);
    cudaGetSymbolAddress((void**)&Vthp, g_Vth);
    cudaGetSymbolAddress((void**)&Vtlp, g_Vtl);
    cudaGetSymbolAddress((void**)&Pfp,  g_Pf);

    cudaFuncSetAttribute(flash_kernel, cudaFuncAttributeMaxDynamicSharedMemorySize, FL_SMEM);

    // ---- all 4 input projections in ONE launch (grid.z = job id) ----
    // Q/K/P: single fp16 (outputs are fp16-rounded downstream anyway).
    // V: bf16x3 (feeds output linearly).
    GemmJobs pj;
    pj.j[0] = { query,   Wq, bq,      Qp,      nullptr,             nullptr, B_ * T_, 0, 1 };
    pj.j[1] = { key_in,  Wk, bk,      nullptr, (__nv_bfloat16*)Kfp, nullptr, B_ * T_, 1, 1 };
    pj.j[2] = { value,   Wv, bv,      nullptr, Vthp,                Vtlp,    B_ * T_, 2, 0 };
    pj.j[3] = { pos_emb, Wp, nullptr, nullptr, (__nv_bfloat16*)Pfp, nullptr, P_,      1, 1 };
    gemm_multi<<<dim3(4, 64, 4), 256>>>(pj);

    // fused attention (scores fp16 + rel-shift + softmax + AV bf16x3)
    flash_kernel<<<dim3(8, B_ * H_), 256, FL_SMEM>>>(pu, pv, mask);

    // output projection: bf16x3 (exact path to the output)
    GemmJobs oj;
    oj.j[0] = { Cp, Wo, bo, out, nullptr, nullptr, B_ * T_, 0, 0 };
    oj.j[1] = oj.j[0]; oj.j[2] = oj.j[0]; oj.j[3] = oj.j[0];
    gemm_multi<<<dim3(4, 64, 1), 256>>>(oj);
}

// round 13
// speedup vs baseline: 1.2402x; 1.2402x over previous
#include <cuda_runtime.h>
#include <cuda_bf16.h>
#include <cuda_fp16.h>
#include <math.h>

#define B_ 8
#define T_ 1024
#define F_ 512
#define H_ 8
#define DK_ 64
#define P_ 2047

// -------- scratch (device globals; no allocations allowed) --------
__device__ float g_Q[(size_t)B_ * T_ * F_];                 // fp32 q proj
__device__ __half g_Kf[(size_t)B_ * T_ * F_];               // k fp16 (scores)
__device__ __half g_Vf[(size_t)B_ * H_ * DK_ * T_];         // v^T fp16 [b,h,d,s]
__device__ __half g_Pf[(size_t)(P_ + 1) * F_];              // p fp16 (row 2047 spare)
__device__ float g_ctx[(size_t)B_ * T_ * F_];

// =====================================================================
// Helpers
// =====================================================================
__device__ __forceinline__ unsigned smem_u32(const void* p) {
    return (unsigned)__cvta_generic_to_shared(p);
}
__device__ __forceinline__ void ldsm_x4(unsigned addr, unsigned& r0, unsigned& r1,
                                        unsigned& r2, unsigned& r3) {
    asm volatile("ldmatrix.sync.aligned.m8n8.x4.shared.b16 {%0,%1,%2,%3}, [%4];"
                 : "=r"(r0), "=r"(r1), "=r"(r2), "=r"(r3) : "r"(addr));
}
__device__ __forceinline__ void ldsm_x2(unsigned addr, unsigned& r0, unsigned& r1) {
    asm volatile("ldmatrix.sync.aligned.m8n8.x2.shared.b16 {%0,%1}, [%2];"
                 : "=r"(r0), "=r"(r1) : "r"(addr));
}
__device__ __forceinline__ void mma_bf16(float& c0, float& c1, float& c2, float& c3,
                                         unsigned a0, unsigned a1, unsigned a2, unsigned a3,
                                         unsigned b0, unsigned b1) {
    asm volatile(
        "mma.sync.aligned.m16n8k16.row.col.f32.bf16.bf16.f32 "
        "{%0,%1,%2,%3},{%4,%5,%6,%7},{%8,%9},{%0,%1,%2,%3};"
        : "+f"(c0), "+f"(c1), "+f"(c2), "+f"(c3)
        : "r"(a0), "r"(a1), "r"(a2), "r"(a3), "r"(b0), "r"(b1));
}
__device__ __forceinline__ void mma_fp16(float& c0, float& c1, float& c2, float& c3,
                                         unsigned a0, unsigned a1, unsigned a2, unsigned a3,
                                         unsigned b0, unsigned b1) {
    asm volatile(
        "mma.sync.aligned.m16n8k16.row.col.f32.f16.f16.f32 "
        "{%0,%1,%2,%3},{%4,%5,%6,%7},{%8,%9},{%0,%1,%2,%3};"
        : "+f"(c0), "+f"(c1), "+f"(c2), "+f"(c3)
        : "r"(a0), "r"(a1), "r"(a2), "r"(a3), "r"(b0), "r"(b1));
}
__device__ __forceinline__ void split_hl(float x, __nv_bfloat16& h, __nv_bfloat16& l) {
    h = __float2bfloat16(x);
    l = __float2bfloat16(x - __bfloat162float(h));
}
__device__ __forceinline__ void cvt4(__nv_bfloat16* dh, __nv_bfloat16* dl, float4 v) {
    float f[4] = {v.x, v.y, v.z, v.w};
#pragma unroll
    for (int i = 0; i < 4; i++) split_hl(f[i], dh[i], dl[i]);
}
__device__ __forceinline__ void pack_f16(float x0, float x1, unsigned& r) {
    __half2 h = __floats2half2_rn(x0, x1);
    r = *(unsigned*)&h;
}
__device__ __forceinline__ void cp16(void* smem_dst, const void* gsrc) {
    unsigned d = smem_u32(smem_dst);
    asm volatile("cp.async.cg.shared.global [%0], [%1], 16;" :: "r"(d), "l"(gsrc));
}

// =====================================================================
// bf16x3 tensor-core NT GEMM, multi-job batched over grid.z (R11 shape).
// mode 0: fp32 -> C. mode 1: fp16 -> (half*)Ch.
// mode 2: fp16 transposed per-head -> (half*)Ch.
// =====================================================================
#define BK_ 32
#define LDSA (BK_ + 8)
#define GN_ 512
#define GK_ 512

struct GemmJob {
    const float* A; const float* W; const float* bias;
    float* C; __nv_bfloat16* Ch; __nv_bfloat16* Cl;
    int M; int mode;
};
struct GemmJobs { GemmJob j[4]; };

__global__ void __launch_bounds__(256) gemm_multi(GemmJobs jobs)
{
    __shared__ __nv_bfloat16 Ah[128][LDSA], Al[128][LDSA];
    __shared__ __nv_bfloat16 Wh[128][LDSA], Wl[128][LDSA];

    const GemmJob job = jobs.j[blockIdx.z];
    const int M = job.M;
    const int m0 = blockIdx.y * 128;
    if (m0 >= M) return;
    const int n0 = blockIdx.x * 128;

    const float* __restrict__ A = job.A;
    const float* __restrict__ W = job.W;

    const int tid = threadIdx.x;
    const int lane = tid & 31;
    const int warp = tid >> 5;
    const int wm = warp & 1;
    const int wn = warp >> 1;

    const int arow = lane & 15;
    const int asel = (lane >> 4) << 3;
    const int bn_off = lane & 7;
    const int bsel = ((lane >> 3) & 1) << 3;

    float acc[4][4][4];
#pragma unroll
    for (int i = 0; i < 4; i++)
#pragma unroll
        for (int j = 0; j < 4; j++)
#pragma unroll
            for (int q = 0; q < 4; q++) acc[i][j][q] = 0.f;

    for (int k0 = 0; k0 < GK_; k0 += BK_) {
#pragma unroll
        for (int q = 0; q < 4; q++) {
            int idx = tid + q * 256;
            int row = idx >> 3;
            int col = (idx & 7) << 2;
            int gm = m0 + row; if (gm >= M) gm = M - 1;
            float4 a4 = *(const float4*)(A + (size_t)gm * GK_ + k0 + col);
            cvt4(&Ah[row][col], &Al[row][col], a4);
            int gn = n0 + row;
            float4 w4 = *(const float4*)(W + (size_t)gn * GK_ + k0 + col);
            cvt4(&Wh[row][col], &Wl[row][col], w4);
        }
        __syncthreads();

#pragma unroll
        for (int kk = 0; kk < 2; kk++) {
            const int kb = kk << 4;
            unsigned ah[4][4], al[4][4], bh[4][2], bl[4][2];
#pragma unroll
            for (int i = 0; i < 4; i++) {
                int r = wm * 64 + i * 16 + arow;
                ldsm_x4(smem_u32(&Ah[r][kb + asel]), ah[i][0], ah[i][1], ah[i][2], ah[i][3]);
                ldsm_x4(smem_u32(&Al[r][kb + asel]), al[i][0], al[i][1], al[i][2], al[i][3]);
            }
#pragma unroll
            for (int j = 0; j < 4; j++) {
                int n = wn * 32 + j * 8 + bn_off;
                ldsm_x2(smem_u32(&Wh[n][kb + bsel]), bh[j][0], bh[j][1]);
                ldsm_x2(smem_u32(&Wl[n][kb + bsel]), bl[j][0], bl[j][1]);
            }
#pragma unroll
            for (int i = 0; i < 4; i++)
#pragma unroll
                for (int j = 0; j < 4; j++) {
                    mma_bf16(acc[i][j][0], acc[i][j][1], acc[i][j][2], acc[i][j][3],
                             ah[i][0], ah[i][1], ah[i][2], ah[i][3], bh[j][0], bh[j][1]);
                    mma_bf16(acc[i][j][0], acc[i][j][1], acc[i][j][2], acc[i][j][3],
                             ah[i][0], ah[i][1], ah[i][2], ah[i][3], bl[j][0], bl[j][1]);
                    mma_bf16(acc[i][j][0], acc[i][j][1], acc[i][j][2], acc[i][j][3],
                             al[i][0], al[i][1], al[i][2], al[i][3], bh[j][0], bh[j][1]);
                }
        }
        __syncthreads();
    }

#pragma unroll
    for (int i = 0; i < 4; i++) {
        int mbase = m0 + wm * 64 + i * 16 + (lane >> 2);
#pragma unroll
        for (int j = 0; j < 4; j++) {
            int n = n0 + wn * 32 + j * 8 + (lane & 3) * 2;
            float bb0 = job.bias ? job.bias[n] : 0.f;
            float bb1 = job.bias ? job.bias[n + 1] : 0.f;
#pragma unroll
            for (int half = 0; half < 2; half++) {
                int m = mbase + half * 8;
                if (m >= M) continue;
                float v0 = acc[i][j][half * 2 + 0] + bb0;
                float v1 = acc[i][j][half * 2 + 1] + bb1;
                if (job.mode == 0) {
                    job.C[(size_t)m * GN_ + n] = v0;
                    job.C[(size_t)m * GN_ + n + 1] = v1;
                } else if (job.mode == 1) {
                    __half2 hv = __floats2half2_rn(v0, v1);
                    *(__half2*)((__half*)job.Ch + (size_t)m * GN_ + n) = hv;
                } else {
                    int bb = m >> 10, ss = m & 1023;
#pragma unroll
                    for (int e = 0; e < 2; e++) {
                        int nn = n + e;
                        int hh = nn >> 6, dd = nn & 63;
                        size_t dst = (((size_t)(bb * H_ + hh) * DK_ + dd) * T_ + ss);
                        ((__half*)job.Ch)[dst] = __float2half(e ? v1 : v0);
                    }
                }
            }
        }
    }
}

// =====================================================================
// Fused flash attention: scores AND AV via single fp16 MMAs (2 chains
// each), cp.async pipelined, 8 warps, 128 t-rows/block. 119KB smem.
// =====================================================================
#define FL_SMEM 119040

__global__ void __launch_bounds__(256) flash_kernel(
    const float* __restrict__ pu, const float* __restrict__ pv,
    const int* __restrict__ mask)
{
    extern __shared__ char sm[];
    __half* KF = (__half*)(sm);                           // 2 x [64][72]
    __half* VF = (__half*)(sm + 18432);                   // 2 x [64 d][72 s]
    __half* PF = (__half*)(sm + 36864);                   // [256][72] circular
    float* GS  = (float*)(sm + 73728);                    // [8 warps][16][88]
    float* MSK = (float*)(sm + 118784);                   // [64]
    // prologue aliases over the PF region (dead before first P prefetch)
    __half* QUF = (__half*)(sm + 36864);                  // [128][72]
    __half* QVF = (__half*)(sm + 55296);

    const int tid = threadIdx.x, lane = tid & 31, warp = tid >> 5;
    const int gid = lane >> 2, tig = lane & 3;
    const int bh = blockIdx.y, b = bh >> 3, h = bh & 7;
    const int t0 = blockIdx.x * 128;
    const int pbase0 = T_ - 1 - t0 - 127;   // >= 0

    // ---- phase 0: qu/qv fp16 staging (scaled by 1/sqrt(DK)=0.125) ----
    for (int x = tid; x < 2048; x += 256) {
        int r = x >> 4, c = (x & 15) << 2;
        float4 q4 = *(const float4*)(g_Q + ((size_t)(b * T_ + t0 + r)) * F_ + h * DK_ + c);
        float4 u4 = *(const float4*)(pu + h * DK_ + c);
        float4 v4 = *(const float4*)(pv + h * DK_ + c);
        float qs[4] = {q4.x, q4.y, q4.z, q4.w};
        float us[4] = {u4.x, u4.y, u4.z, u4.w};
        float vs[4] = {v4.x, v4.y, v4.z, v4.w};
#pragma unroll
        for (int e = 0; e < 4; e++) {
            QUF[r * 72 + c + e] = __float2half((qs[e] + us[e]) * 0.125f);
            QVF[r * 72 + c + e] = __float2half((qs[e] + vs[e]) * 0.125f);
        }
    }
    __syncthreads();

    unsigned quf[4][4], qvf[4][4];
    {
        int ar = warp * 16 + (lane & 15);
        int ac = (lane >> 4) << 3;
#pragma unroll
        for (int kc = 0; kc < 4; kc++) {
            ldsm_x4(smem_u32(&QUF[ar * 72 + kc * 16 + ac]), quf[kc][0], quf[kc][1], quf[kc][2], quf[kc][3]);
            ldsm_x4(smem_u32(&QVF[ar * 72 + kc * 16 + ac]), qvf[kc][0], qvf[kc][1], qvf[kc][2], qvf[kc][3]);
        }
    }
    __syncthreads();   // PF region free from here on

    // ---- initial prefetch: tile 0 K/V (buf 0) + P rows [0,192) ----
    for (int x = tid; x < 512; x += 256) {
        int r = x >> 3, c = (x & 7) << 3;
        size_t ksrc = ((size_t)(b * T_ + r)) * F_ + h * DK_ + c;
        cp16(&KF[r * 72 + c], g_Kf + ksrc);
        size_t vsrc = ((size_t)bh * DK_ + r) * T_ + c;
        cp16(&VF[r * 72 + c], g_Vf + vsrc);
    }
    for (int x = tid; x < 1536; x += 256) {
        int rr = x >> 3, c = (x & 7) << 3;
        int grow = pbase0 + rr; if (grow > P_) grow = P_;
        cp16(&PF[rr * 72 + c], g_Pf + (size_t)grow * F_ + h * DK_ + c);
    }
    asm volatile("cp.async.commit_group;");

    float o[8][4], oL[8][4];
#pragma unroll
    for (int nt = 0; nt < 8; nt++)
#pragma unroll
        for (int q = 0; q < 4; q++) { o[nt][q] = 0.f; oL[nt][q] = 0.f; }
    float mr0 = -1e30f, mr1 = -1e30f, l0 = 0.f, l1 = 0.f;
    float* GSw = GS + warp * (16 * 88);

    for (int i = 0; i < 16; i++) {
        const int s0 = i * 64;

        // ---- prefetch tile i+1 ----
        if (i < 15) {
            __half* kf = KF + ((i + 1) & 1) * 4608;
            __half* vf = VF + ((i + 1) & 1) * 4608;
            int s0n = s0 + 64;
            for (int x = tid; x < 512; x += 256) {
                int r = x >> 3, c = (x & 7) << 3;
                size_t ksrc = ((size_t)(b * T_ + s0n + r)) * F_ + h * DK_ + c;
                cp16(&kf[r * 72 + c], g_Kf + ksrc);
                size_t vsrc = ((size_t)bh * DK_ + r) * T_ + s0n + c;
                cp16(&vf[r * 72 + c], g_Vf + vsrc);
            }
            int u0 = 192 + 64 * i;
            for (int x = tid; x < 512; x += 256) {
                int rr = x >> 3, c = (x & 7) << 3;
                int un = u0 + rr;
                int slot = un & 255;
                int grow = pbase0 + un; if (grow > P_) grow = P_;
                cp16(&PF[slot * 72 + c], g_Pf + (size_t)grow * F_ + h * DK_ + c);
            }
            asm volatile("cp.async.commit_group;");
        }
        if (tid < 64) MSK[tid] = (mask[b * T_ + s0 + tid] == 0) ? -3.0e38f : 0.f;
        if (i < 15) asm volatile("cp.async.wait_group 1;" ::: "memory");
        else        asm volatile("cp.async.wait_group 0;" ::: "memory");
        __syncthreads();

        const __half* kf = KF + (i & 1) * 4608;
        const __half* vf = VF + (i & 1) * 4608;
        const int off = (64 * i) & 255;

        // ---- G = qv_strip @ Pwin^T (banded BD, fp16, 2 chains) ----
        {
            int prow = 112 - 16 * warp + (lane & 7);
            int psel = ((lane >> 3) & 1) << 3;
#pragma unroll
            for (int nt = 0; nt < 10; nt++) {
                float gA0 = 0.f, gA1 = 0.f, gA2 = 0.f, gA3 = 0.f;
                float gB0 = 0.f, gB1 = 0.f, gB2 = 0.f, gB3 = 0.f;
                int prw = (prow + nt * 8 + off) & 255;
#pragma unroll
                for (int kc = 0; kc < 4; kc += 2) {
                    unsigned p0, p1, p2, p3;
                    ldsm_x2(smem_u32(&PF[prw * 72 + kc * 16 + psel]), p0, p1);
                    ldsm_x2(smem_u32(&PF[prw * 72 + (kc + 1) * 16 + psel]), p2, p3);
                    mma_fp16(gA0, gA1, gA2, gA3, qvf[kc][0], qvf[kc][1], qvf[kc][2], qvf[kc][3], p0, p1);
                    mma_fp16(gB0, gB1, gB2, gB3, qvf[kc + 1][0], qvf[kc + 1][1], qvf[kc + 1][2], qvf[kc + 1][3], p2, p3);
                }
                int gc = nt * 8 + 2 * tig;
                GSw[gid * 88 + gc] = gA0 + gB0;
                GSw[gid * 88 + gc + 1] = gA1 + gB1;
                GSw[(gid + 8) * 88 + gc] = gA2 + gB2;
                GSw[(gid + 8) * 88 + gc + 1] = gA3 + gB3;
            }
        }
        __syncwarp();

        // ---- S = qu @ K^T + band(G) + mask (fp16, 2 chains) ----
        float sf[8][4];
        {
            int krow = lane & 7;
            int ksel = ((lane >> 3) & 1) << 3;
#pragma unroll
            for (int nt = 0; nt < 8; nt++) {
                float aA0 = 0.f, aA1 = 0.f, aA2 = 0.f, aA3 = 0.f;
                float aB0 = 0.f, aB1 = 0.f, aB2 = 0.f, aB3 = 0.f;
#pragma unroll
                for (int kc = 0; kc < 4; kc += 2) {
                    unsigned k0, k1, k2, k3;
                    ldsm_x2(smem_u32(&kf[(nt * 8 + krow) * 72 + kc * 16 + ksel]), k0, k1);
                    ldsm_x2(smem_u32(&kf[(nt * 8 + krow) * 72 + (kc + 1) * 16 + ksel]), k2, k3);
                    mma_fp16(aA0, aA1, aA2, aA3, quf[kc][0], quf[kc][1], quf[kc][2], quf[kc][3], k0, k1);
                    mma_fp16(aB0, aB1, aB2, aB3, quf[kc + 1][0], quf[kc + 1][1], quf[kc + 1][2], quf[kc + 1][3], k2, k3);
                }
                int col = nt * 8 + 2 * tig;
                sf[nt][0] = aA0 + aB0 + GSw[gid * 88 + col - gid + 15] + MSK[col];
                sf[nt][1] = aA1 + aB1 + GSw[gid * 88 + col - gid + 16] + MSK[col + 1];
                sf[nt][2] = aA2 + aB2 + GSw[(gid + 8) * 88 + col - gid + 7] + MSK[col];
                sf[nt][3] = aA3 + aB3 + GSw[(gid + 8) * 88 + col - gid + 8] + MSK[col + 1];
            }
        }

        // ---- online softmax ----
        float mx0 = -1e30f, mx1 = -1e30f;
#pragma unroll
        for (int nt = 0; nt < 8; nt++) {
            mx0 = fmaxf(mx0, fmaxf(sf[nt][0], sf[nt][1]));
            mx1 = fmaxf(mx1, fmaxf(sf[nt][2], sf[nt][3]));
        }
        mx0 = fmaxf(mx0, __shfl_xor_sync(0xffffffffu, mx0, 1));
        mx0 = fmaxf(mx0, __shfl_xor_sync(0xffffffffu, mx0, 2));
        mx1 = fmaxf(mx1, __shfl_xor_sync(0xffffffffu, mx1, 1));
        mx1 = fmaxf(mx1, __shfl_xor_sync(0xffffffffu, mx1, 2));
        float mn0 = fmaxf(mr0, mx0), mn1 = fmaxf(mr1, mx1);
        float sc0 = __expf(mr0 - mn0), sc1 = __expf(mr1 - mn1);
        float su0 = 0.f, su1 = 0.f;
#pragma unroll
        for (int nt = 0; nt < 8; nt++) {
            sf[nt][0] = __expf(sf[nt][0] - mn0);
            sf[nt][1] = __expf(sf[nt][1] - mn0);
            sf[nt][2] = __expf(sf[nt][2] - mn1);
            sf[nt][3] = __expf(sf[nt][3] - mn1);
            su0 += sf[nt][0] + sf[nt][1];
            su1 += sf[nt][2] + sf[nt][3];
        }
        su0 += __shfl_xor_sync(0xffffffffu, su0, 1);
        su0 += __shfl_xor_sync(0xffffffffu, su0, 2);
        su1 += __shfl_xor_sync(0xffffffffu, su1, 1);
        su1 += __shfl_xor_sync(0xffffffffu, su1, 2);
        l0 = l0 * sc0 + su0;
        l1 = l1 * sc1 + su1;
        mr0 = mn0; mr1 = mn1;
#pragma unroll
        for (int nt = 0; nt < 8; nt++) {
            o[nt][0] *= sc0;  o[nt][1] *= sc0;
            o[nt][2] *= sc1;  o[nt][3] *= sc1;
            oL[nt][0] *= sc0; oL[nt][1] *= sc0;
            oL[nt][2] *= sc1; oL[nt][3] *= sc1;
        }

        // ---- O += P @ V (fp16 single, 2 chains by kc parity) ----
        {
            int vrow = lane & 7;
            int vsel = ((lane >> 3) & 1) << 3;
#pragma unroll
            for (int kc = 0; kc < 4; kc++) {
                unsigned af[4];
                pack_f16(sf[2 * kc][0], sf[2 * kc][1], af[0]);
                pack_f16(sf[2 * kc][2], sf[2 * kc][3], af[1]);
                pack_f16(sf[2 * kc + 1][0], sf[2 * kc + 1][1], af[2]);
                pack_f16(sf[2 * kc + 1][2], sf[2 * kc + 1][3], af[3]);
                float (*acc)[4] = (kc & 1) ? oL : o;
#pragma unroll
                for (int nt = 0; nt < 8; nt++) {
                    unsigned v0, v1;
                    ldsm_x2(smem_u32(&vf[(nt * 8 + vrow) * 72 + kc * 16 + vsel]), v0, v1);
                    mma_fp16(acc[nt][0], acc[nt][1], acc[nt][2], acc[nt][3],
                             af[0], af[1], af[2], af[3], v0, v1);
                }
            }
        }
        __syncthreads();
    }

    // ---- epilogue ----
    float inv0 = (l0 > 0.f) ? 1.f / l0 : 0.f;
    float inv1 = (l1 > 0.f) ? 1.f / l1 : 0.f;
    int row0 = t0 + warp * 16 + gid;
#pragma unroll
    for (int nt = 0; nt < 8; nt++) {
        int colg = h * DK_ + nt * 8 + 2 * tig;
        float2 w0 = make_float2((o[nt][0] + oL[nt][0]) * inv0, (o[nt][1] + oL[nt][1]) * inv0);
        *(float2*)&g_ctx[((size_t)(b * T_ + row0)) * F_ + colg] = w0;
        float2 w1 = make_float2((o[nt][2] + oL[nt][2]) * inv1, (o[nt][3] + oL[nt][3]) * inv1);
        *(float2*)&g_ctx[((size_t)(b * T_ + row0 + 8)) * F_ + colg] = w1;
    }
}

// =====================================================================
extern "C" void kernel_launch(void* const* d_in, const int* in_sizes, int n_in,
                              void* d_out, int out_size)
{
    const float* query   = (const float*)d_in[0];
    const float* key_in  = (const float*)d_in[1];
    const float* value   = (const float*)d_in[2];
    const float* pos_emb = (const float*)d_in[3];
    const int*   mask    = (const int*)d_in[4];
    const float* Wq = (const float*)d_in[5];
    const float* bq = (const float*)d_in[6];
    const float* Wk = (const float*)d_in[7];
    const float* bk = (const float*)d_in[8];
    const float* Wv = (const float*)d_in[9];
    const float* bv = (const float*)d_in[10];
    const float* Wo = (const float*)d_in[11];
    const float* bo = (const float*)d_in[12];
    const float* Wp = (const float*)d_in[13];
    const float* pu = (const float*)d_in[14];
    const float* pv = (const float*)d_in[15];
    float* out = (float*)d_out;

    float *Qp, *Cp;
    __half *Kfp, *Vfp, *Pfp;
    cudaGetSymbolAddress((void**)&Qp,  g_Q);
    cudaGetSymbolAddress((void**)&Cp,  g_ctx);
    cudaGetSymbolAddress((void**)&Kfp, g_Kf);
    cudaGetSymbolAddress((void**)&Vfp, g_Vf);
    cudaGetSymbolAddress((void**)&Pfp, g_Pf);

    cudaFuncSetAttribute(flash_kernel, cudaFuncAttributeMaxDynamicSharedMemorySize, FL_SMEM);

    // ---- all 4 input projections in ONE launch (all bf16x3 compute) ----
    GemmJobs pj;
    pj.j[0] = { query,   Wq, bq,      Qp,      nullptr,             nullptr, B_ * T_, 0 };
    pj.j[1] = { key_in,  Wk, bk,      nullptr, (__nv_bfloat16*)Kfp, nullptr, B_ * T_, 1 };
    pj.j[2] = { value,   Wv, bv,      nullptr, (__nv_bfloat16*)Vfp, nullptr, B_ * T_, 2 };
    pj.j[3] = { pos_emb, Wp, nullptr, nullptr, (__nv_bfloat16*)Pfp, nullptr, P_,      1 };
    gemm_multi<<<dim3(4, 64, 4), 256>>>(pj);

    // fused attention (scores fp16 + rel-shift + softmax + AV fp16)
    flash_kernel<<<dim3(8, B_ * H_), 256, FL_SMEM>>>(pu, pv, mask);

    // output projection: bf16x3 (exact path to the output)
    GemmJobs oj;
    oj.j[0] = { Cp, Wo, bo, out, nullptr, nullptr, B_ * T_, 0 };
    oj.j[1] = oj.j[0]; oj.j[2] = oj.j[0]; oj.j[3] = oj.j[0];
    gemm_multi<<<dim3(4, 64, 1), 256>>>(oj);
}

// round 14
// speedup vs baseline: 1.7142x; 1.3822x over previous
#include <cuda_runtime.h>
#include <cuda_bf16.h>
#include <cuda_fp16.h>
#include <math.h>

#define B_ 8
#define T_ 1024
#define F_ 512
#define H_ 8
#define DK_ 64
#define P_ 2047

// -------- scratch (device globals; no allocations allowed) --------
__device__ __half g_Xq[(size_t)B_ * T_ * F_];   // fp16 inputs (prepass)
__device__ __half g_Xk[(size_t)B_ * T_ * F_];
__device__ __half g_Xv[(size_t)B_ * T_ * F_];
__device__ __half g_Xp[(size_t)2048 * F_];
__device__ __half g_Wq[(size_t)F_ * F_];        // fp16 weights (prepass)
__device__ __half g_Wk[(size_t)F_ * F_];
__device__ __half g_Wv[(size_t)F_ * F_];
__device__ __half g_Wp[(size_t)F_ * F_];
__device__ __half g_Wo[(size_t)F_ * F_];
__device__ __half g_Qf[(size_t)B_ * T_ * F_];   // q proj (fp16)
__device__ __half g_Kf[(size_t)B_ * T_ * F_];   // k proj (fp16)
__device__ __half g_Vf[(size_t)B_ * H_ * DK_ * T_]; // v^T fp16 [b,h,d,s]
__device__ __half g_Pf[(size_t)(P_ + 1) * F_];  // p proj (fp16, row 2047 spare)
__device__ __half g_Cf[(size_t)B_ * T_ * F_];   // ctx fp16 (flash out)

// =====================================================================
// Helpers
// =====================================================================
__device__ __forceinline__ unsigned smem_u32(const void* p) {
    return (unsigned)__cvta_generic_to_shared(p);
}
__device__ __forceinline__ void ldsm_x4(unsigned addr, unsigned& r0, unsigned& r1,
                                        unsigned& r2, unsigned& r3) {
    asm volatile("ldmatrix.sync.aligned.m8n8.x4.shared.b16 {%0,%1,%2,%3}, [%4];"
                 : "=r"(r0), "=r"(r1), "=r"(r2), "=r"(r3) : "r"(addr));
}
__device__ __forceinline__ void ldsm_x2(unsigned addr, unsigned& r0, unsigned& r1) {
    asm volatile("ldmatrix.sync.aligned.m8n8.x2.shared.b16 {%0,%1}, [%2];"
                 : "=r"(r0), "=r"(r1) : "r"(addr));
}
__device__ __forceinline__ void mma_fp16(float& c0, float& c1, float& c2, float& c3,
                                         unsigned a0, unsigned a1, unsigned a2, unsigned a3,
                                         unsigned b0, unsigned b1) {
    asm volatile(
        "mma.sync.aligned.m16n8k16.row.col.f32.f16.f16.f32 "
        "{%0,%1,%2,%3},{%4,%5,%6,%7},{%8,%9},{%0,%1,%2,%3};"
        : "+f"(c0), "+f"(c1), "+f"(c2), "+f"(c3)
        : "r"(a0), "r"(a1), "r"(a2), "r"(a3), "r"(b0), "r"(b1));
}
__device__ __forceinline__ void pack_f16(float x0, float x1, unsigned& r) {
    __half2 h = __floats2half2_rn(x0, x1);
    r = *(unsigned*)&h;
}
__device__ __forceinline__ void cp16(void* smem_dst, const void* gsrc) {
    unsigned d = smem_u32(smem_dst);
    asm volatile("cp.async.cg.shared.global [%0], [%1], 16;" :: "r"(d), "l"(gsrc));
}

// =====================================================================
// Prepass: fp32 -> fp16 conversion (4 inputs + 5 weights)
// =====================================================================
struct CvtJob { const float* src; __half* dst; int n4; };
struct CvtJobs { CvtJob j[9]; };

__global__ void __launch_bounds__(256) cvt_f16(CvtJobs jobs)
{
    const CvtJob jb = jobs.j[blockIdx.y];
    const int stride = gridDim.x * blockDim.x;
    for (int i = blockIdx.x * blockDim.x + threadIdx.x; i < jb.n4; i += stride) {
        float4 v = ((const float4*)jb.src)[i];
        __half2 a = __floats2half2_rn(v.x, v.y);
        __half2 b = __floats2half2_rn(v.z, v.w);
        *(uint2*)(jb.dst + (size_t)i * 4) = make_uint2(*(unsigned*)&a, *(unsigned*)&b);
    }
}

// =====================================================================
// fp16 x1 tensor-core NT GEMM, cp.async double-buffered, multi-job.
// C[M,512] = A[M,512] @ W[512,512]^T (+bias). 256 thr, 8 warps,
// block 128x128, warp tile 64x32, BK=32, 41KB smem (2 bufs).
// mode 0: fp32 -> C. mode 1: fp16 -> Ch. mode 2: fp16 V^T per-head -> Ch.
// =====================================================================
struct GemmJob {
    const __half* A; const __half* W; const float* bias;
    float* C; __half* Ch;
    int M; int mode;
};
struct GemmJobs { GemmJob j[4]; };

__global__ void __launch_bounds__(256) gemm_f16(GemmJobs jobs)
{
    __shared__ __half gsm[20480];   // 2 bufs x (A 5120 + W 5120) halves

    const GemmJob job = jobs.j[blockIdx.z];
    const int M = job.M;
    const int m0 = blockIdx.y * 128;
    if (m0 >= M) return;
    const int n0 = blockIdx.x * 128;

    const int tid = threadIdx.x, lane = tid & 31, warp = tid >> 5;
    const int wm = warp & 1, wn = warp >> 1;
    const int arow = lane & 15;
    const int asel = (lane >> 4) << 3;
    const int bn_off = lane & 7;
    const int bsel = ((lane >> 3) & 1) << 3;

    float acc[4][4][4];
#pragma unroll
    for (int i = 0; i < 4; i++)
#pragma unroll
        for (int j = 0; j < 4; j++)
#pragma unroll
            for (int q = 0; q < 4; q++) acc[i][j][q] = 0.f;

    // stage k-chunk s into buffer s&1 via cp.async (4 cp16 per thread)
#define STAGE(s) do {                                                        \
        int _buf = (s) & 1, _k0 = (s) * 32;                                  \
        _Pragma("unroll")                                                    \
        for (int _t = 0; _t < 4; _t++) {                                     \
            int _i = tid + _t * 256;                                         \
            int _isW = _i >> 9, _j = _i & 511;                               \
            int _r = _j >> 2, _cc = (_j & 3) << 3;                           \
            const __half* _src;                                              \
            if (_isW) {                                                      \
                _src = job.W + (size_t)(n0 + _r) * 512 + _k0 + _cc;          \
            } else {                                                         \
                int _gm = m0 + _r; if (_gm >= M) _gm = M - 1;                \
                _src = job.A + (size_t)_gm * 512 + _k0 + _cc;                \
            }                                                                \
            cp16(&gsm[_buf * 10240 + _isW * 5120 + _r * 40 + _cc], _src);    \
        }                                                                    \
        asm volatile("cp.async.commit_group;");                              \
    } while (0)

    STAGE(0);

    for (int s = 0; s < 16; s++) {
        if (s < 15) {
            STAGE(s + 1);
            asm volatile("cp.async.wait_group 1;" ::: "memory");
        } else {
            asm volatile("cp.async.wait_group 0;" ::: "memory");
        }
        __syncthreads();
        const __half* SA = gsm + (s & 1) * 10240;
        const __half* SW = SA + 5120;

#pragma unroll
        for (int kk = 0; kk < 2; kk++) {
            const int kb = kk << 4;
            unsigned ah[4][4], bh[4][2];
#pragma unroll
            for (int i = 0; i < 4; i++) {
                int r = wm * 64 + i * 16 + arow;
                ldsm_x4(smem_u32(&SA[r * 40 + kb + asel]),
                        ah[i][0], ah[i][1], ah[i][2], ah[i][3]);
            }
#pragma unroll
            for (int j = 0; j < 4; j++) {
                int n = wn * 32 + j * 8 + bn_off;
                ldsm_x2(smem_u32(&SW[n * 40 + kb + bsel]), bh[j][0], bh[j][1]);
            }
#pragma unroll
            for (int i = 0; i < 4; i++)
#pragma unroll
                for (int j = 0; j < 4; j++)
                    mma_fp16(acc[i][j][0], acc[i][j][1], acc[i][j][2], acc[i][j][3],
                             ah[i][0], ah[i][1], ah[i][2], ah[i][3], bh[j][0], bh[j][1]);
        }
        __syncthreads();
    }
#undef STAGE

    // ---- epilogue ----
#pragma unroll
    for (int i = 0; i < 4; i++) {
        int mbase = m0 + wm * 64 + i * 16 + (lane >> 2);
#pragma unroll
        for (int j = 0; j < 4; j++) {
            int n = n0 + wn * 32 + j * 8 + (lane & 3) * 2;
            float bb0 = job.bias ? job.bias[n] : 0.f;
            float bb1 = job.bias ? job.bias[n + 1] : 0.f;
#pragma unroll
            for (int half = 0; half < 2; half++) {
                int m = mbase + half * 8;
                if (m >= M) continue;
                float v0 = acc[i][j][half * 2 + 0] + bb0;
                float v1 = acc[i][j][half * 2 + 1] + bb1;
                if (job.mode == 0) {
                    job.C[(size_t)m * 512 + n] = v0;
                    job.C[(size_t)m * 512 + n + 1] = v1;
                } else if (job.mode == 1) {
                    __half2 hv = __floats2half2_rn(v0, v1);
                    *(__half2*)(job.Ch + (size_t)m * 512 + n) = hv;
                } else {
                    int bb = m >> 10, ss = m & 1023;
#pragma unroll
                    for (int e = 0; e < 2; e++) {
                        int nn = n + e;
                        int hh = nn >> 6, dd = nn & 63;
                        size_t dst = (((size_t)(bb * H_ + hh) * DK_ + dd) * T_ + ss);
                        job.Ch[dst] = __float2half(e ? v1 : v0);
                    }
                }
            }
        }
    }
}

// =====================================================================
// Fused flash attention: scores + AV all single fp16 MMAs (2 chains),
// cp.async pipelined, 8 warps, 128 t-rows/block. 119KB smem.
// Reads fp16 Q, writes fp16 ctx.
// =====================================================================
#define FL_SMEM 119040

__global__ void __launch_bounds__(256) flash_kernel(
    const float* __restrict__ pu, const float* __restrict__ pv,
    const int* __restrict__ mask)
{
    extern __shared__ char sm[];
    __half* KF = (__half*)(sm);                           // 2 x [64][72]
    __half* VF = (__half*)(sm + 18432);                   // 2 x [64 d][72 s]
    __half* PF = (__half*)(sm + 36864);                   // [256][72] circular
    float* GS  = (float*)(sm + 73728);                    // [8 warps][16][88]
    float* MSK = (float*)(sm + 118784);                   // [64]
    // prologue aliases over the PF region (dead before first P prefetch)
    __half* QUF = (__half*)(sm + 36864);                  // [128][72]
    __half* QVF = (__half*)(sm + 55296);

    const int tid = threadIdx.x, lane = tid & 31, warp = tid >> 5;
    const int gid = lane >> 2, tig = lane & 3;
    const int bh = blockIdx.y, b = bh >> 3, h = bh & 7;
    const int t0 = blockIdx.x * 128;
    const int pbase0 = T_ - 1 - t0 - 127;   // >= 0

    // ---- phase 0: qu/qv fp16 staging (scaled by 1/sqrt(DK)=0.125) ----
    for (int x = tid; x < 2048; x += 256) {
        int r = x >> 4, c = (x & 15) << 2;
        uint2 qraw = *(const uint2*)(g_Qf + ((size_t)(b * T_ + t0 + r)) * F_ + h * DK_ + c);
        __half2 q01 = *(__half2*)&qraw.x;
        __half2 q23 = *(__half2*)&qraw.y;
        float qs[4] = {__low2float(q01), __high2float(q01),
                       __low2float(q23), __high2float(q23)};
        float4 u4 = *(const float4*)(pu + h * DK_ + c);
        float4 v4 = *(const float4*)(pv + h * DK_ + c);
        float us[4] = {u4.x, u4.y, u4.z, u4.w};
        float vs[4] = {v4.x, v4.y, v4.z, v4.w};
#pragma unroll
        for (int e = 0; e < 4; e++) {
            QUF[r * 72 + c + e] = __float2half((qs[e] + us[e]) * 0.125f);
            QVF[r * 72 + c + e] = __float2half((qs[e] + vs[e]) * 0.125f);
        }
    }
    __syncthreads();

    unsigned quf[4][4], qvf[4][4];
    {
        int ar = warp * 16 + (lane & 15);
        int ac = (lane >> 4) << 3;
#pragma unroll
        for (int kc = 0; kc < 4; kc++) {
            ldsm_x4(smem_u32(&QUF[ar * 72 + kc * 16 + ac]), quf[kc][0], quf[kc][1], quf[kc][2], quf[kc][3]);
            ldsm_x4(smem_u32(&QVF[ar * 72 + kc * 16 + ac]), qvf[kc][0], qvf[kc][1], qvf[kc][2], qvf[kc][3]);
        }
    }
    __syncthreads();   // PF region free from here on

    // ---- initial prefetch: tile 0 K/V (buf 0) + P rows [0,192) ----
    for (int x = tid; x < 512; x += 256) {
        int r = x >> 3, c = (x & 7) << 3;
        size_t ksrc = ((size_t)(b * T_ + r)) * F_ + h * DK_ + c;
        cp16(&KF[r * 72 + c], g_Kf + ksrc);
        size_t vsrc = ((size_t)bh * DK_ + r) * T_ + c;
        cp16(&VF[r * 72 + c], g_Vf + vsrc);
    }
    for (int x = tid; x < 1536; x += 256) {
        int rr = x >> 3, c = (x & 7) << 3;
        int grow = pbase0 + rr; if (grow > P_) grow = P_;
        cp16(&PF[rr * 72 + c], g_Pf + (size_t)grow * F_ + h * DK_ + c);
    }
    asm volatile("cp.async.commit_group;");

    float o[8][4], oL[8][4];
#pragma unroll
    for (int nt = 0; nt < 8; nt++)
#pragma unroll
        for (int q = 0; q < 4; q++) { o[nt][q] = 0.f; oL[nt][q] = 0.f; }
    float mr0 = -1e30f, mr1 = -1e30f, l0 = 0.f, l1 = 0.f;
    float* GSw = GS + warp * (16 * 88);

    for (int i = 0; i < 16; i++) {
        const int s0 = i * 64;

        // ---- prefetch tile i+1 ----
        if (i < 15) {
            __half* kf = KF + ((i + 1) & 1) * 4608;
            __half* vf = VF + ((i + 1) & 1) * 4608;
            int s0n = s0 + 64;
            for (int x = tid; x < 512; x += 256) {
                int r = x >> 3, c = (x & 7) << 3;
                size_t ksrc = ((size_t)(b * T_ + s0n + r)) * F_ + h * DK_ + c;
                cp16(&kf[r * 72 + c], g_Kf + ksrc);
                size_t vsrc = ((size_t)bh * DK_ + r) * T_ + s0n + c;
                cp16(&vf[r * 72 + c], g_Vf + vsrc);
            }
            int u0 = 192 + 64 * i;
            for (int x = tid; x < 512; x += 256) {
                int rr = x >> 3, c = (x & 7) << 3;
                int un = u0 + rr;
                int slot = un & 255;
                int grow = pbase0 + un; if (grow > P_) grow = P_;
                cp16(&PF[slot * 72 + c], g_Pf + (size_t)grow * F_ + h * DK_ + c);
            }
            asm volatile("cp.async.commit_group;");
        }
        if (tid < 64) MSK[tid] = (mask[b * T_ + s0 + tid] == 0) ? -3.0e38f : 0.f;
        if (i < 15) asm volatile("cp.async.wait_group 1;" ::: "memory");
        else        asm volatile("cp.async.wait_group 0;" ::: "memory");
        __syncthreads();

        const __half* kf = KF + (i & 1) * 4608;
        const __half* vf = VF + (i & 1) * 4608;
        const int off = (64 * i) & 255;

        // ---- G = qv_strip @ Pwin^T (banded BD, fp16, 2 chains) ----
        {
            int prow = 112 - 16 * warp + (lane & 7);
            int psel = ((lane >> 3) & 1) << 3;
#pragma unroll
            for (int nt = 0; nt < 10; nt++) {
                float gA0 = 0.f, gA1 = 0.f, gA2 = 0.f, gA3 = 0.f;
                float gB0 = 0.f, gB1 = 0.f, gB2 = 0.f, gB3 = 0.f;
                int prw = (prow + nt * 8 + off) & 255;
#pragma unroll
                for (int kc = 0; kc < 4; kc += 2) {
                    unsigned p0, p1, p2, p3;
                    ldsm_x2(smem_u32(&PF[prw * 72 + kc * 16 + psel]), p0, p1);
                    ldsm_x2(smem_u32(&PF[prw * 72 + (kc + 1) * 16 + psel]), p2, p3);
                    mma_fp16(gA0, gA1, gA2, gA3, qvf[kc][0], qvf[kc][1], qvf[kc][2], qvf[kc][3], p0, p1);
                    mma_fp16(gB0, gB1, gB2, gB3, qvf[kc + 1][0], qvf[kc + 1][1], qvf[kc + 1][2], qvf[kc + 1][3], p2, p3);
                }
                int gc = nt * 8 + 2 * tig;
                GSw[gid * 88 + gc] = gA0 + gB0;
                GSw[gid * 88 + gc + 1] = gA1 + gB1;
                GSw[(gid + 8) * 88 + gc] = gA2 + gB2;
                GSw[(gid + 8) * 88 + gc + 1] = gA3 + gB3;
            }
        }
        __syncwarp();

        // ---- S = qu @ K^T + band(G) + mask (fp16, 2 chains) ----
        float sf[8][4];
        {
            int krow = lane & 7;
            int ksel = ((lane >> 3) & 1) << 3;
#pragma unroll
            for (int nt = 0; nt < 8; nt++) {
                float aA0 = 0.f, aA1 = 0.f, aA2 = 0.f, aA3 = 0.f;
                float aB0 = 0.f, aB1 = 0.f, aB2 = 0.f, aB3 = 0.f;
#pragma unroll
                for (int kc = 0; kc < 4; kc += 2) {
                    unsigned k0, k1, k2, k3;
                    ldsm_x2(smem_u32(&kf[(nt * 8 + krow) * 72 + kc * 16 + ksel]), k0, k1);
                    ldsm_x2(smem_u32(&kf[(nt * 8 + krow) * 72 + (kc + 1) * 16 + ksel]), k2, k3);
                    mma_fp16(aA0, aA1, aA2, aA3, quf[kc][0], quf[kc][1], quf[kc][2], quf[kc][3], k0, k1);
                    mma_fp16(aB0, aB1, aB2, aB3, quf[kc + 1][0], quf[kc + 1][1], quf[kc + 1][2], quf[kc + 1][3], k2, k3);
                }
                int col = nt * 8 + 2 * tig;
                sf[nt][0] = aA0 + aB0 + GSw[gid * 88 + col - gid + 15] + MSK[col];
                sf[nt][1] = aA1 + aB1 + GSw[gid * 88 + col - gid + 16] + MSK[col + 1];
                sf[nt][2] = aA2 + aB2 + GSw[(gid + 8) * 88 + col - gid + 7] + MSK[col];
                sf[nt][3] = aA3 + aB3 + GSw[(gid + 8) * 88 + col - gid + 8] + MSK[col + 1];
            }
        }

        // ---- online softmax ----
        float mx0 = -1e30f, mx1 = -1e30f;
#pragma unroll
        for (int nt = 0; nt < 8; nt++) {
            mx0 = fmaxf(mx0, fmaxf(sf[nt][0], sf[nt][1]));
            mx1 = fmaxf(mx1, fmaxf(sf[nt][2], sf[nt][3]));
        }
        mx0 = fmaxf(mx0, __shfl_xor_sync(0xffffffffu, mx0, 1));
        mx0 = fmaxf(mx0, __shfl_xor_sync(0xffffffffu, mx0, 2));
        mx1 = fmaxf(mx1, __shfl_xor_sync(0xffffffffu, mx1, 1));
        mx1 = fmaxf(mx1, __shfl_xor_sync(0xffffffffu, mx1, 2));
        float mn0 = fmaxf(mr0, mx0), mn1 = fmaxf(mr1, mx1);
        float sc0 = __expf(mr0 - mn0), sc1 = __expf(mr1 - mn1);
        float su0 = 0.f, su1 = 0.f;
#pragma unroll
        for (int nt = 0; nt < 8; nt++) {
            sf[nt][0] = __expf(sf[nt][0] - mn0);
            sf[nt][1] = __expf(sf[nt][1] - mn0);
            sf[nt][2] = __expf(sf[nt][2] - mn1);
            sf[nt][3] = __expf(sf[nt][3] - mn1);
            su0 += sf[nt][0] + sf[nt][1];
            su1 += sf[nt][2] + sf[nt][3];
        }
        su0 += __shfl_xor_sync(0xffffffffu, su0, 1);
        su0 += __shfl_xor_sync(0xffffffffu, su0, 2);
        su1 += __shfl_xor_sync(0xffffffffu, su1, 1);
        su1 += __shfl_xor_sync(0xffffffffu, su1, 2);
        l0 = l0 * sc0 + su0;
        l1 = l1 * sc1 + su1;
        mr0 = mn0; mr1 = mn1;
#pragma unroll
        for (int nt = 0; nt < 8; nt++) {
            o[nt][0] *= sc0;  o[nt][1] *= sc0;
            o[nt][2] *= sc1;  o[nt][3] *= sc1;
            oL[nt][0] *= sc0; oL[nt][1] *= sc0;
            oL[nt][2] *= sc1; oL[nt][3] *= sc1;
        }

        // ---- O += P @ V (fp16, 2 chains by kc parity) ----
        {
            int vrow = lane & 7;
            int vsel = ((lane >> 3) & 1) << 3;
#pragma unroll
            for (int kc = 0; kc < 4; kc++) {
                unsigned af[4];
                pack_f16(sf[2 * kc][0], sf[2 * kc][1], af[0]);
                pack_f16(sf[2 * kc][2], sf[2 * kc][3], af[1]);
                pack_f16(sf[2 * kc + 1][0], sf[2 * kc + 1][1], af[2]);
                pack_f16(sf[2 * kc + 1][2], sf[2 * kc + 1][3], af[3]);
                float (*acc)[4] = (kc & 1) ? oL : o;
#pragma unroll
                for (int nt = 0; nt < 8; nt++) {
                    unsigned v0, v1;
                    ldsm_x2(smem_u32(&vf[(nt * 8 + vrow) * 72 + kc * 16 + vsel]), v0, v1);
                    mma_fp16(acc[nt][0], acc[nt][1], acc[nt][2], acc[nt][3],
                             af[0], af[1], af[2], af[3], v0, v1);
                }
            }
        }
        __syncthreads();
    }

    // ---- epilogue: write ctx fp16 ----
    float inv0 = (l0 > 0.f) ? 1.f / l0 : 0.f;
    float inv1 = (l1 > 0.f) ? 1.f / l1 : 0.f;
    int row0 = t0 + warp * 16 + gid;
#pragma unroll
    for (int nt = 0; nt < 8; nt++) {
        int colg = h * DK_ + nt * 8 + 2 * tig;
        __half2 w0 = __floats2half2_rn((o[nt][0] + oL[nt][0]) * inv0,
                                       (o[nt][1] + oL[nt][1]) * inv0);
        *(__half2*)&g_Cf[((size_t)(b * T_ + row0)) * F_ + colg] = w0;
        __half2 w1 = __floats2half2_rn((o[nt][2] + oL[nt][2]) * inv1,
                                       (o[nt][3] + oL[nt][3]) * inv1);
        *(__half2*)&g_Cf[((size_t)(b * T_ + row0 + 8)) * F_ + colg] = w1;
    }
}

// =====================================================================
extern "C" void kernel_launch(void* const* d_in, const int* in_sizes, int n_in,
                              void* d_out, int out_size)
{
    const float* query   = (const float*)d_in[0];
    const float* key_in  = (const float*)d_in[1];
    const float* value   = (const float*)d_in[2];
    const float* pos_emb = (const float*)d_in[3];
    const int*   mask    = (const int*)d_in[4];
    const float* Wq = (const float*)d_in[5];
    const float* bq = (const float*)d_in[6];
    const float* Wk = (const float*)d_in[7];
    const float* bk = (const float*)d_in[8];
    const float* Wv = (const float*)d_in[9];
    const float* bv = (const float*)d_in[10];
    const float* Wo = (const float*)d_in[11];
    const float* bo = (const float*)d_in[12];
    const float* Wp = (const float*)d_in[13];
    const float* pu = (const float*)d_in[14];
    const float* pv = (const float*)d_in[15];
    float* out = (float*)d_out;

    __half *Xq, *Xk, *Xv, *Xp, *Wqf, *Wkf, *Wvf, *Wpf, *Wof;
    __half *Qfp, *Kfp, *Vfp, *Pfp, *Cfp;
    cudaGetSymbolAddress((void**)&Xq,  g_Xq);
    cudaGetSymbolAddress((void**)&Xk,  g_Xk);
    cudaGetSymbolAddress((void**)&Xv,  g_Xv);
    cudaGetSymbolAddress((void**)&Xp,  g_Xp);
    cudaGetSymbolAddress((void**)&Wqf, g_Wq);
    cudaGetSymbolAddress((void**)&Wkf, g_Wk);
    cudaGetSymbolAddress((void**)&Wvf, g_Wv);
    cudaGetSymbolAddress((void**)&Wpf, g_Wp);
    cudaGetSymbolAddress((void**)&Wof, g_Wo);
    cudaGetSymbolAddress((void**)&Qfp, g_Qf);
    cudaGetSymbolAddress((void**)&Kfp, g_Kf);
    cudaGetSymbolAddress((void**)&Vfp, g_Vf);
    cudaGetSymbolAddress((void**)&Pfp, g_Pf);
    cudaGetSymbolAddress((void**)&Cfp, g_Cf);

    cudaFuncSetAttribute(flash_kernel, cudaFuncAttributeMaxDynamicSharedMemorySize, FL_SMEM);

    // ---- prepass: fp32 -> fp16 for all GEMM operands ----
    const int NBT = B_ * T_ * F_ / 4;
    const int NP  = P_ * F_ / 4;
    const int NW  = F_ * F_ / 4;
    CvtJobs cj;
    cj.j[0] = { query,   Xq,  NBT };
    cj.j[1] = { key_in,  Xk,  NBT };
    cj.j[2] = { value,   Xv,  NBT };
    cj.j[3] = { pos_emb, Xp,  NP  };
    cj.j[4] = { Wq, Wqf, NW };
    cj.j[5] = { Wk, Wkf, NW };
    cj.j[6] = { Wv, Wvf, NW };
    cj.j[7] = { Wp, Wpf, NW };
    cj.j[8] = { Wo, Wof, NW };
    cvt_f16<<<dim3(256, 9), 256>>>(cj);

    // ---- all 4 input projections in ONE launch (fp16 x1, cp.async) ----
    GemmJobs pj;
    pj.j[0] = { Xq, Wqf, bq,      nullptr, Qfp, B_ * T_, 1 };
    pj.j[1] = { Xk, Wkf, bk,      nullptr, Kfp, B_ * T_, 1 };
    pj.j[2] = { Xv, Wvf, bv,      nullptr, Vfp, B_ * T_, 2 };
    pj.j[3] = { Xp, Wpf, nullptr, nullptr, Pfp, P_,      1 };
    gemm_f16<<<dim3(4, 64, 4), 256>>>(pj);

    // fused attention (all fp16 MMA paths)
    flash_kernel<<<dim3(8, B_ * H_), 256, FL_SMEM>>>(pu, pv, mask);

    // output projection (fp16 x1, fp32 out)
    GemmJobs oj;
    oj.j[0] = { Cfp, Wof, bo, out, nullptr, B_ * T_, 0 };
    oj.j[1] = oj.j[0]; oj.j[2] = oj.j[0]; oj.j[3] = oj.j[0];
    gemm_f16<<<dim3(4, 64, 1), 256>>>(oj);
}

// round 15
// speedup vs baseline: 1.7482x; 1.0199x over previous
#include <cuda_runtime.h>
#include <cuda_bf16.h>
#include <cuda_fp16.h>
#include <math.h>

#define B_ 8
#define T_ 1024
#define F_ 512
#define H_ 8
#define DK_ 64
#define P_ 2047

// -------- scratch (device globals; no allocations allowed) --------
__device__ __half g_Xq[(size_t)B_ * T_ * F_];   // fp16 inputs (prepass)
__device__ __half g_Xk[(size_t)B_ * T_ * F_];
__device__ __half g_Xv[(size_t)B_ * T_ * F_];
__device__ __half g_Xp[(size_t)2048 * F_];
__device__ __half g_Wq[(size_t)F_ * F_];        // fp16 weights (prepass)
__device__ __half g_Wk[(size_t)F_ * F_];
__device__ __half g_Wv[(size_t)F_ * F_];
__device__ __half g_Wp[(size_t)F_ * F_];
__device__ __half g_Wo[(size_t)F_ * F_];
__device__ __half g_Qf[(size_t)B_ * T_ * F_];   // q proj (fp16)
__device__ __half g_Kf[(size_t)B_ * T_ * F_];   // k proj (fp16)
__device__ __half g_Vf[(size_t)B_ * H_ * DK_ * T_]; // v^T fp16 [b,h,d,s]
__device__ __half g_Pf[(size_t)(P_ + 1) * F_];  // p proj (fp16, row 2047 spare)
__device__ __half g_Cf[(size_t)B_ * T_ * F_];   // ctx fp16 (flash out)

// =====================================================================
// Helpers
// =====================================================================
__device__ __forceinline__ unsigned smem_u32(const void* p) {
    return (unsigned)__cvta_generic_to_shared(p);
}
__device__ __forceinline__ void ldsm_x4(unsigned addr, unsigned& r0, unsigned& r1,
                                        unsigned& r2, unsigned& r3) {
    asm volatile("ldmatrix.sync.aligned.m8n8.x4.shared.b16 {%0,%1,%2,%3}, [%4];"
                 : "=r"(r0), "=r"(r1), "=r"(r2), "=r"(r3) : "r"(addr));
}
__device__ __forceinline__ void ldsm_x2(unsigned addr, unsigned& r0, unsigned& r1) {
    asm volatile("ldmatrix.sync.aligned.m8n8.x2.shared.b16 {%0,%1}, [%2];"
                 : "=r"(r0), "=r"(r1) : "r"(addr));
}
__device__ __forceinline__ void mma_fp16(float& c0, float& c1, float& c2, float& c3,
                                         unsigned a0, unsigned a1, unsigned a2, unsigned a3,
                                         unsigned b0, unsigned b1) {
    asm volatile(
        "mma.sync.aligned.m16n8k16.row.col.f32.f16.f16.f32 "
        "{%0,%1,%2,%3},{%4,%5,%6,%7},{%8,%9},{%0,%1,%2,%3};"
        : "+f"(c0), "+f"(c1), "+f"(c2), "+f"(c3)
        : "r"(a0), "r"(a1), "r"(a2), "r"(a3), "r"(b0), "r"(b1));
}
__device__ __forceinline__ void pack_f16(float x0, float x1, unsigned& r) {
    __half2 h = __floats2half2_rn(x0, x1);
    r = *(unsigned*)&h;
}
__device__ __forceinline__ void cp16(void* smem_dst, const void* gsrc) {
    unsigned d = smem_u32(smem_dst);
    asm volatile("cp.async.cg.shared.global [%0], [%1], 16;" :: "r"(d), "l"(gsrc));
}

// =====================================================================
// Prepass: fp32 -> fp16 conversion (4 inputs + 5 weights)
// =====================================================================
struct CvtJob { const float* src; __half* dst; int n4; };
struct CvtJobs { CvtJob j[9]; };

__global__ void __launch_bounds__(256) cvt_f16(CvtJobs jobs)
{
    const CvtJob jb = jobs.j[blockIdx.y];
    const int stride = gridDim.x * blockDim.x;
    for (int i = blockIdx.x * blockDim.x + threadIdx.x; i < jb.n4; i += stride) {
        float4 v = ((const float4*)jb.src)[i];
        __half2 a = __floats2half2_rn(v.x, v.y);
        __half2 b = __floats2half2_rn(v.z, v.w);
        *(uint2*)(jb.dst + (size_t)i * 4) = make_uint2(*(unsigned*)&a, *(unsigned*)&b);
    }
}

// =====================================================================
// fp16 x1 tensor-core NT GEMM, cp.async double-buffered (unchanged R14).
// =====================================================================
struct GemmJob {
    const __half* A; const __half* W; const float* bias;
    float* C; __half* Ch;
    int M; int mode;
};
struct GemmJobs { GemmJob j[4]; };

__global__ void __launch_bounds__(256) gemm_f16(GemmJobs jobs)
{
    __shared__ __half gsm[20480];

    const GemmJob job = jobs.j[blockIdx.z];
    const int M = job.M;
    const int m0 = blockIdx.y * 128;
    if (m0 >= M) return;
    const int n0 = blockIdx.x * 128;

    const int tid = threadIdx.x, lane = tid & 31, warp = tid >> 5;
    const int wm = warp & 1, wn = warp >> 1;
    const int arow = lane & 15;
    const int asel = (lane >> 4) << 3;
    const int bn_off = lane & 7;
    const int bsel = ((lane >> 3) & 1) << 3;

    float acc[4][4][4];
#pragma unroll
    for (int i = 0; i < 4; i++)
#pragma unroll
        for (int j = 0; j < 4; j++)
#pragma unroll
            for (int q = 0; q < 4; q++) acc[i][j][q] = 0.f;

#define STAGE(s) do {                                                        \
        int _buf = (s) & 1, _k0 = (s) * 32;                                  \
        _Pragma("unroll")                                                    \
        for (int _t = 0; _t < 4; _t++) {                                     \
            int _i = tid + _t * 256;                                         \
            int _isW = _i >> 9, _j = _i & 511;                               \
            int _r = _j >> 2, _cc = (_j & 3) << 3;                           \
            const __half* _src;                                              \
            if (_isW) {                                                      \
                _src = job.W + (size_t)(n0 + _r) * 512 + _k0 + _cc;          \
            } else {                                                         \
                int _gm = m0 + _r; if (_gm >= M) _gm = M - 1;                \
                _src = job.A + (size_t)_gm * 512 + _k0 + _cc;                \
            }                                                                \
            cp16(&gsm[_buf * 10240 + _isW * 5120 + _r * 40 + _cc], _src);    \
        }                                                                    \
        asm volatile("cp.async.commit_group;");                              \
    } while (0)

    STAGE(0);

    for (int s = 0; s < 16; s++) {
        if (s < 15) {
            STAGE(s + 1);
            asm volatile("cp.async.wait_group 1;" ::: "memory");
        } else {
            asm volatile("cp.async.wait_group 0;" ::: "memory");
        }
        __syncthreads();
        const __half* SA = gsm + (s & 1) * 10240;
        const __half* SW = SA + 5120;

#pragma unroll
        for (int kk = 0; kk < 2; kk++) {
            const int kb = kk << 4;
            unsigned ah[4][4], bh[4][2];
#pragma unroll
            for (int i = 0; i < 4; i++) {
                int r = wm * 64 + i * 16 + arow;
                ldsm_x4(smem_u32(&SA[r * 40 + kb + asel]),
                        ah[i][0], ah[i][1], ah[i][2], ah[i][3]);
            }
#pragma unroll
            for (int j = 0; j < 4; j++) {
                int n = wn * 32 + j * 8 + bn_off;
                ldsm_x2(smem_u32(&SW[n * 40 + kb + bsel]), bh[j][0], bh[j][1]);
            }
#pragma unroll
            for (int i = 0; i < 4; i++)
#pragma unroll
                for (int j = 0; j < 4; j++)
                    mma_fp16(acc[i][j][0], acc[i][j][1], acc[i][j][2], acc[i][j][3],
                             ah[i][0], ah[i][1], ah[i][2], ah[i][3], bh[j][0], bh[j][1]);
        }
        __syncthreads();
    }
#undef STAGE

#pragma unroll
    for (int i = 0; i < 4; i++) {
        int mbase = m0 + wm * 64 + i * 16 + (lane >> 2);
#pragma unroll
        for (int j = 0; j < 4; j++) {
            int n = n0 + wn * 32 + j * 8 + (lane & 3) * 2;
            float bb0 = job.bias ? job.bias[n] : 0.f;
            float bb1 = job.bias ? job.bias[n + 1] : 0.f;
#pragma unroll
            for (int half = 0; half < 2; half++) {
                int m = mbase + half * 8;
                if (m >= M) continue;
                float v0 = acc[i][j][half * 2 + 0] + bb0;
                float v1 = acc[i][j][half * 2 + 1] + bb1;
                if (job.mode == 0) {
                    job.C[(size_t)m * 512 + n] = v0;
                    job.C[(size_t)m * 512 + n + 1] = v1;
                } else if (job.mode == 1) {
                    __half2 hv = __floats2half2_rn(v0, v1);
                    *(__half2*)(job.Ch + (size_t)m * 512 + n) = hv;
                } else {
                    int bb = m >> 10, ss = m & 1023;
#pragma unroll
                    for (int e = 0; e < 2; e++) {
                        int nn = n + e;
                        int hh = nn >> 6, dd = nn & 63;
                        size_t dst = (((size_t)(bb * H_ + hh) * DK_ + dd) * T_ + ss);
                        job.Ch[dst] = __float2half(e ? v1 : v0);
                    }
                }
            }
        }
    }
}

// =====================================================================
// Fused flash attention: 64 t-rows / 4 warps per block, grid (16, B*H),
// 96.5KB smem -> 2 CTAs/SM. fp16 MMAs everywhere, cp.async pipelined.
// Band constants from the R5-validated 64-row variant.
// =====================================================================
#define FL_SMEM 96512

__global__ void __launch_bounds__(128) flash_kernel(
    const float* __restrict__ pu, const float* __restrict__ pv,
    const int* __restrict__ mask)
{
    extern __shared__ char sm[];
    __half* KF = (__half*)(sm);                           // 2 x [64][72]
    __half* VF = (__half*)(sm + 18432);                   // 2 x [64 d][72 s]
    __half* PF = (__half*)(sm + 36864);                   // [256][72] circular
    float* GS  = (float*)(sm + 73728);                    // [4 warps][16][88]
    float* MSK = (float*)(sm + 96256);                    // [64]
    // prologue aliases over the PF region (dead before first P prefetch)
    __half* QUF = (__half*)(sm + 36864);                  // [64][72]
    __half* QVF = (__half*)(sm + 46080);

    const int tid = threadIdx.x, lane = tid & 31, warp = tid >> 5;
    const int gid = lane >> 2, tig = lane & 3;
    const int bh = blockIdx.y, b = bh >> 3, h = bh & 7;
    const int t0 = blockIdx.x * 64;
    const int pbase0 = T_ - 1 - t0 - 63;    // >= 0

    // ---- phase 0: qu/qv fp16 staging (scaled by 1/sqrt(DK)=0.125) ----
    for (int x = tid; x < 1024; x += 128) {
        int r = x >> 4, c = (x & 15) << 2;
        uint2 qraw = *(const uint2*)(g_Qf + ((size_t)(b * T_ + t0 + r)) * F_ + h * DK_ + c);
        __half2 q01 = *(__half2*)&qraw.x;
        __half2 q23 = *(__half2*)&qraw.y;
        float qs[4] = {__low2float(q01), __high2float(q01),
                       __low2float(q23), __high2float(q23)};
        float4 u4 = *(const float4*)(pu + h * DK_ + c);
        float4 v4 = *(const float4*)(pv + h * DK_ + c);
        float us[4] = {u4.x, u4.y, u4.z, u4.w};
        float vs[4] = {v4.x, v4.y, v4.z, v4.w};
#pragma unroll
        for (int e = 0; e < 4; e++) {
            QUF[r * 72 + c + e] = __float2half((qs[e] + us[e]) * 0.125f);
            QVF[r * 72 + c + e] = __float2half((qs[e] + vs[e]) * 0.125f);
        }
    }
    __syncthreads();

    unsigned quf[4][4], qvf[4][4];
    {
        int ar = warp * 16 + (lane & 15);
        int ac = (lane >> 4) << 3;
#pragma unroll
        for (int kc = 0; kc < 4; kc++) {
            ldsm_x4(smem_u32(&QUF[ar * 72 + kc * 16 + ac]), quf[kc][0], quf[kc][1], quf[kc][2], quf[kc][3]);
            ldsm_x4(smem_u32(&QVF[ar * 72 + kc * 16 + ac]), qvf[kc][0], qvf[kc][1], qvf[kc][2], qvf[kc][3]);
        }
    }
    __syncthreads();   // PF region free from here on

    // ---- initial prefetch: tile 0 K/V (buf 0) + P window rows [0,128) ----
    for (int x = tid; x < 512; x += 128) {
        int r = x >> 3, c = (x & 7) << 3;
        size_t ksrc = ((size_t)(b * T_ + r)) * F_ + h * DK_ + c;
        cp16(&KF[r * 72 + c], g_Kf + ksrc);
        size_t vsrc = ((size_t)bh * DK_ + r) * T_ + c;
        cp16(&VF[r * 72 + c], g_Vf + vsrc);
    }
    for (int x = tid; x < 1024; x += 128) {
        int rr = x >> 3, c = (x & 7) << 3;
        int grow = pbase0 + rr; if (grow > P_) grow = P_;
        cp16(&PF[rr * 72 + c], g_Pf + (size_t)grow * F_ + h * DK_ + c);
    }
    asm volatile("cp.async.commit_group;");

    float o[8][4], oL[8][4];
#pragma unroll
    for (int nt = 0; nt < 8; nt++)
#pragma unroll
        for (int q = 0; q < 4; q++) { o[nt][q] = 0.f; oL[nt][q] = 0.f; }
    float mr0 = -1e30f, mr1 = -1e30f, l0 = 0.f, l1 = 0.f;
    float* GSw = GS + warp * (16 * 88);

    for (int i = 0; i < 16; i++) {
        const int s0 = i * 64;

        // ---- prefetch tile i+1 (K/V buf flip + 64 new P rows) ----
        if (i < 15) {
            __half* kf = KF + ((i + 1) & 1) * 4608;
            __half* vf = VF + ((i + 1) & 1) * 4608;
            int s0n = s0 + 64;
            for (int x = tid; x < 512; x += 128) {
                int r = x >> 3, c = (x & 7) << 3;
                size_t ksrc = ((size_t)(b * T_ + s0n + r)) * F_ + h * DK_ + c;
                cp16(&kf[r * 72 + c], g_Kf + ksrc);
                size_t vsrc = ((size_t)bh * DK_ + r) * T_ + s0n + c;
                cp16(&vf[r * 72 + c], g_Vf + vsrc);
            }
            int u0 = 128 + 64 * i;
            for (int x = tid; x < 512; x += 128) {
                int rr = x >> 3, c = (x & 7) << 3;
                int un = u0 + rr;
                int slot = un & 255;
                int grow = pbase0 + un; if (grow > P_) grow = P_;
                cp16(&PF[slot * 72 + c], g_Pf + (size_t)grow * F_ + h * DK_ + c);
            }
            asm volatile("cp.async.commit_group;");
        }
        if (tid < 64) MSK[tid] = (mask[b * T_ + s0 + tid] == 0) ? -3.0e38f : 0.f;
        if (i < 15) asm volatile("cp.async.wait_group 1;" ::: "memory");
        else        asm volatile("cp.async.wait_group 0;" ::: "memory");
        __syncthreads();

        const __half* kf = KF + (i & 1) * 4608;
        const __half* vf = VF + (i & 1) * 4608;
        const int off = (64 * i) & 255;

        // ---- G = qv_strip @ Pwin^T (banded BD, fp16, 2 chains) ----
        {
            int prow = 48 - 16 * warp + (lane & 7);
            int psel = ((lane >> 3) & 1) << 3;
#pragma unroll
            for (int nt = 0; nt < 10; nt++) {
                float gA0 = 0.f, gA1 = 0.f, gA2 = 0.f, gA3 = 0.f;
                float gB0 = 0.f, gB1 = 0.f, gB2 = 0.f, gB3 = 0.f;
                int prw = (prow + nt * 8 + off) & 255;
#pragma unroll
                for (int kc = 0; kc < 4; kc += 2) {
                    unsigned p0, p1, p2, p3;
                    ldsm_x2(smem_u32(&PF[prw * 72 + kc * 16 + psel]), p0, p1);
                    ldsm_x2(smem_u32(&PF[prw * 72 + (kc + 1) * 16 + psel]), p2, p3);
                    mma_fp16(gA0, gA1, gA2, gA3, qvf[kc][0], qvf[kc][1], qvf[kc][2], qvf[kc][3], p0, p1);
                    mma_fp16(gB0, gB1, gB2, gB3, qvf[kc + 1][0], qvf[kc + 1][1], qvf[kc + 1][2], qvf[kc + 1][3], p2, p3);
                }
                int gc = nt * 8 + 2 * tig;
                GSw[gid * 88 + gc] = gA0 + gB0;
                GSw[gid * 88 + gc + 1] = gA1 + gB1;
                GSw[(gid + 8) * 88 + gc] = gA2 + gB2;
                GSw[(gid + 8) * 88 + gc + 1] = gA3 + gB3;
            }
        }
        __syncwarp();

        // ---- S = qu @ K^T + band(G) + mask (fp16, 2 chains) ----
        float sf[8][4];
        {
            int krow = lane & 7;
            int ksel = ((lane >> 3) & 1) << 3;
#pragma unroll
            for (int nt = 0; nt < 8; nt++) {
                float aA0 = 0.f, aA1 = 0.f, aA2 = 0.f, aA3 = 0.f;
                float aB0 = 0.f, aB1 = 0.f, aB2 = 0.f, aB3 = 0.f;
#pragma unroll
                for (int kc = 0; kc < 4; kc += 2) {
                    unsigned k0, k1, k2, k3;
                    ldsm_x2(smem_u32(&kf[(nt * 8 + krow) * 72 + kc * 16 + ksel]), k0, k1);
                    ldsm_x2(smem_u32(&kf[(nt * 8 + krow) * 72 + (kc + 1) * 16 + ksel]), k2, k3);
                    mma_fp16(aA0, aA1, aA2, aA3, quf[kc][0], quf[kc][1], quf[kc][2], quf[kc][3], k0, k1);
                    mma_fp16(aB0, aB1, aB2, aB3, quf[kc + 1][0], quf[kc + 1][1], quf[kc + 1][2], quf[kc + 1][3], k2, k3);
                }
                int col = nt * 8 + 2 * tig;
                sf[nt][0] = aA0 + aB0 + GSw[gid * 88 + col - gid + 15] + MSK[col];
                sf[nt][1] = aA1 + aB1 + GSw[gid * 88 + col - gid + 16] + MSK[col + 1];
                sf[nt][2] = aA2 + aB2 + GSw[(gid + 8) * 88 + col - gid + 7] + MSK[col];
                sf[nt][3] = aA3 + aB3 + GSw[(gid + 8) * 88 + col - gid + 8] + MSK[col + 1];
            }
        }

        // ---- online softmax ----
        float mx0 = -1e30f, mx1 = -1e30f;
#pragma unroll
        for (int nt = 0; nt < 8; nt++) {
            mx0 = fmaxf(mx0, fmaxf(sf[nt][0], sf[nt][1]));
            mx1 = fmaxf(mx1, fmaxf(sf[nt][2], sf[nt][3]));
        }
        mx0 = fmaxf(mx0, __shfl_xor_sync(0xffffffffu, mx0, 1));
        mx0 = fmaxf(mx0, __shfl_xor_sync(0xffffffffu, mx0, 2));
        mx1 = fmaxf(mx1, __shfl_xor_sync(0xffffffffu, mx1, 1));
        mx1 = fmaxf(mx1, __shfl_xor_sync(0xffffffffu, mx1, 2));
        float mn0 = fmaxf(mr0, mx0), mn1 = fmaxf(mr1, mx1);
        float sc0 = __expf(mr0 - mn0), sc1 = __expf(mr1 - mn1);
        float su0 = 0.f, su1 = 0.f;
#pragma unroll
        for (int nt = 0; nt < 8; nt++) {
            sf[nt][0] = __expf(sf[nt][0] - mn0);
            sf[nt][1] = __expf(sf[nt][1] - mn0);
            sf[nt][2] = __expf(sf[nt][2] - mn1);
            sf[nt][3] = __expf(sf[nt][3] - mn1);
            su0 += sf[nt][0] + sf[nt][1];
            su1 += sf[nt][2] + sf[nt][3];
        }
        su0 += __shfl_xor_sync(0xffffffffu, su0, 1);
        su0 += __shfl_xor_sync(0xffffffffu, su0, 2);
        su1 += __shfl_xor_sync(0xffffffffu, su1, 1);
        su1 += __shfl_xor_sync(0xffffffffu, su1, 2);
        l0 = l0 * sc0 + su0;
        l1 = l1 * sc1 + su1;
        mr0 = mn0; mr1 = mn1;
#pragma unroll
        for (int nt = 0; nt < 8; nt++) {
            o[nt][0] *= sc0;  o[nt][1] *= sc0;
            o[nt][2] *= sc1;  o[nt][3] *= sc1;
            oL[nt][0] *= sc0; oL[nt][1] *= sc0;
            oL[nt][2] *= sc1; oL[nt][3] *= sc1;
        }

        // ---- O += P @ V (fp16, 2 chains by kc parity) ----
        {
            int vrow = lane & 7;
            int vsel = ((lane >> 3) & 1) << 3;
#pragma unroll
            for (int kc = 0; kc < 4; kc++) {
                unsigned af[4];
                pack_f16(sf[2 * kc][0], sf[2 * kc][1], af[0]);
                pack_f16(sf[2 * kc][2], sf[2 * kc][3], af[1]);
                pack_f16(sf[2 * kc + 1][0], sf[2 * kc + 1][1], af[2]);
                pack_f16(sf[2 * kc + 1][2], sf[2 * kc + 1][3], af[3]);
                float (*acc)[4] = (kc & 1) ? oL : o;
#pragma unroll
                for (int nt = 0; nt < 8; nt++) {
                    unsigned v0, v1;
                    ldsm_x2(smem_u32(&vf[(nt * 8 + vrow) * 72 + kc * 16 + vsel]), v0, v1);
                    mma_fp16(acc[nt][0], acc[nt][1], acc[nt][2], acc[nt][3],
                             af[0], af[1], af[2], af[3], v0, v1);
                }
            }
        }
        __syncthreads();
    }

    // ---- epilogue: write ctx fp16 ----
    float inv0 = (l0 > 0.f) ? 1.f / l0 : 0.f;
    float inv1 = (l1 > 0.f) ? 1.f / l1 : 0.f;
    int row0 = t0 + warp * 16 + gid;
#pragma unroll
    for (int nt = 0; nt < 8; nt++) {
        int colg = h * DK_ + nt * 8 + 2 * tig;
        __half2 w0 = __floats2half2_rn((o[nt][0] + oL[nt][0]) * inv0,
                                       (o[nt][1] + oL[nt][1]) * inv0);
        *(__half2*)&g_Cf[((size_t)(b * T_ + row0)) * F_ + colg] = w0;
        __half2 w1 = __floats2half2_rn((o[nt][2] + oL[nt][2]) * inv1,
                                       (o[nt][3] + oL[nt][3]) * inv1);
        *(__half2*)&g_Cf[((size_t)(b * T_ + row0 + 8)) * F_ + colg] = w1;
    }
}

// =====================================================================
extern "C" void kernel_launch(void* const* d_in, const int* in_sizes, int n_in,
                              void* d_out, int out_size)
{
    const float* query   = (const float*)d_in[0];
    const float* key_in  = (const float*)d_in[1];
    const float* value   = (const float*)d_in[2];
    const float* pos_emb = (const float*)d_in[3];
    const int*   mask    = (const int*)d_in[4];
    const float* Wq = (const float*)d_in[5];
    const float* bq = (const float*)d_in[6];
    const float* Wk = (const float*)d_in[7];
    const float* bk = (const float*)d_in[8];
    const float* Wv = (const float*)d_in[9];
    const float* bv = (const float*)d_in[10];
    const float* Wo = (const float*)d_in[11];
    const float* bo = (const float*)d_in[12];
    const float* Wp = (const float*)d_in[13];
    const float* pu = (const float*)d_in[14];
    const float* pv = (const float*)d_in[15];
    float* out = (float*)d_out;

    __half *Xq, *Xk, *Xv, *Xp, *Wqf, *Wkf, *Wvf, *Wpf, *Wof;
    __half *Qfp, *Kfp, *Vfp, *Pfp, *Cfp;
    cudaGetSymbolAddress((void**)&Xq,  g_Xq);
    cudaGetSymbolAddress((void**)&Xk,  g_Xk);
    cudaGetSymbolAddress((void**)&Xv,  g_Xv);
    cudaGetSymbolAddress((void**)&Xp,  g_Xp);
    cudaGetSymbolAddress((void**)&Wqf, g_Wq);
    cudaGetSymbolAddress((void**)&Wkf, g_Wk);
    cudaGetSymbolAddress((void**)&Wvf, g_Wv);
    cudaGetSymbolAddress((void**)&Wpf, g_Wp);
    cudaGetSymbolAddress((void**)&Wof, g_Wo);
    cudaGetSymbolAddress((void**)&Qfp, g_Qf);
    cudaGetSymbolAddress((void**)&Kfp, g_Kf);
    cudaGetSymbolAddress((void**)&Vfp, g_Vf);
    cudaGetSymbolAddress((void**)&Pfp, g_Pf);
    cudaGetSymbolAddress((void**)&Cfp, g_Cf);

    cudaFuncSetAttribute(flash_kernel, cudaFuncAttributeMaxDynamicSharedMemorySize, FL_SMEM);

    // ---- prepass: fp32 -> fp16 for all GEMM operands ----
    const int NBT = B_ * T_ * F_ / 4;
    const int NP  = P_ * F_ / 4;
    const int NW  = F_ * F_ / 4;
    CvtJobs cj;
    cj.j[0] = { query,   Xq,  NBT };
    cj.j[1] = { key_in,  Xk,  NBT };
    cj.j[2] = { value,   Xv,  NBT };
    cj.j[3] = { pos_emb, Xp,  NP  };
    cj.j[4] = { Wq, Wqf, NW };
    cj.j[5] = { Wk, Wkf, NW };
    cj.j[6] = { Wv, Wvf, NW };
    cj.j[7] = { Wp, Wpf, NW };
    cj.j[8] = { Wo, Wof, NW };
    cvt_f16<<<dim3(256, 9), 256>>>(cj);

    // ---- all 4 input projections in ONE launch (fp16 x1, cp.async) ----
    GemmJobs pj;
    pj.j[0] = { Xq, Wqf, bq,      nullptr, Qfp, B_ * T_, 1 };
    pj.j[1] = { Xk, Wkf, bk,      nullptr, Kfp, B_ * T_, 1 };
    pj.j[2] = { Xv, Wvf, bv,      nullptr, Vfp, B_ * T_, 2 };
    pj.j[3] = { Xp, Wpf, nullptr, nullptr, Pfp, P_,      1 };
    gemm_f16<<<dim3(4, 64, 4), 256>>>(pj);

    // fused attention (all fp16, 2 CTAs/SM)
    flash_kernel<<<dim3(16, B_ * H_), 128, FL_SMEM>>>(pu, pv, mask);

    // output projection (fp16 x1, fp32 out)
    GemmJobs oj;
    oj.j[0] = { Cfp, Wof, bo, out, nullptr, B_ * T_, 0 };
    oj.j[1] = oj.j[0]; oj.j[2] = oj.j[0]; oj.j[3] = oj.j[0];
    gemm_f16<<<dim3(4, 64, 1), 256>>>(oj);
}

// round 16
// speedup vs baseline: 1.8581x; 1.0628x over previous
#include <cuda_runtime.h>
#include <cuda_bf16.h>
#include <cuda_fp16.h>
#include <math.h>

#define B_ 8
#define T_ 1024
#define F_ 512
#define H_ 8
#define DK_ 64
#define P_ 2047

// -------- scratch (device globals; no allocations allowed) --------
__device__ __half g_Xq[(size_t)B_ * T_ * F_];   // fp16 inputs (prepass)
__device__ __half g_Xk[(size_t)B_ * T_ * F_];
__device__ __half g_Xv[(size_t)B_ * T_ * F_];
__device__ __half g_Xp[(size_t)2048 * F_];
__device__ __half g_Wq[(size_t)F_ * F_];        // fp16 weights (prepass)
__device__ __half g_Wk[(size_t)F_ * F_];
__device__ __half g_Wv[(size_t)F_ * F_];
__device__ __half g_Wp[(size_t)F_ * F_];
__device__ __half g_Wo[(size_t)F_ * F_];
__device__ __half g_Qf[(size_t)B_ * T_ * F_];   // q proj (fp16)
__device__ __half g_Kf[(size_t)B_ * T_ * F_];   // k proj (fp16)
__device__ __half g_Vf[(size_t)B_ * H_ * DK_ * T_]; // v^T fp16 [b,h,d,s]
__device__ __half g_Pf[(size_t)(P_ + 1) * F_];  // p proj (fp16, row 2047 = 0)
__device__ __half g_Cf[(size_t)B_ * T_ * F_];   // ctx fp16 (flash out)

// =====================================================================
// Helpers
// =====================================================================
__device__ __forceinline__ unsigned smem_u32(const void* p) {
    return (unsigned)__cvta_generic_to_shared(p);
}
__device__ __forceinline__ void ldsm_x4(unsigned addr, unsigned& r0, unsigned& r1,
                                        unsigned& r2, unsigned& r3) {
    asm volatile("ldmatrix.sync.aligned.m8n8.x4.shared.b16 {%0,%1,%2,%3}, [%4];"
                 : "=r"(r0), "=r"(r1), "=r"(r2), "=r"(r3) : "r"(addr));
}
__device__ __forceinline__ void ldsm_x2(unsigned addr, unsigned& r0, unsigned& r1) {
    asm volatile("ldmatrix.sync.aligned.m8n8.x2.shared.b16 {%0,%1}, [%2];"
                 : "=r"(r0), "=r"(r1) : "r"(addr));
}
__device__ __forceinline__ void mma_fp16(float& c0, float& c1, float& c2, float& c3,
                                         unsigned a0, unsigned a1, unsigned a2, unsigned a3,
                                         unsigned b0, unsigned b1) {
    asm volatile(
        "mma.sync.aligned.m16n8k16.row.col.f32.f16.f16.f32 "
        "{%0,%1,%2,%3},{%4,%5,%6,%7},{%8,%9},{%0,%1,%2,%3};"
        : "+f"(c0), "+f"(c1), "+f"(c2), "+f"(c3)
        : "r"(a0), "r"(a1), "r"(a2), "r"(a3), "r"(b0), "r"(b1));
}
__device__ __forceinline__ void pack_f16(float x0, float x1, unsigned& r) {
    __half2 h = __floats2half2_rn(x0, x1);
    r = *(unsigned*)&h;
}
__device__ __forceinline__ void cp16(void* smem_dst, const void* gsrc) {
    unsigned d = smem_u32(smem_dst);
    asm volatile("cp.async.cg.shared.global [%0], [%1], 16;" :: "r"(d), "l"(gsrc));
}

// =====================================================================
// Prepass: fp32 -> fp16 conversion (4 inputs + 5 weights)
// =====================================================================
struct CvtJob { const float* src; __half* dst; int n4; };
struct CvtJobs { CvtJob j[9]; };

__global__ void __launch_bounds__(256) cvt_f16(CvtJobs jobs)
{
    const CvtJob jb = jobs.j[blockIdx.y];
    const int stride = gridDim.x * blockDim.x;
    for (int i = blockIdx.x * blockDim.x + threadIdx.x; i < jb.n4; i += stride) {
        float4 v = ((const float4*)jb.src)[i];
        __half2 a = __floats2half2_rn(v.x, v.y);
        __half2 b = __floats2half2_rn(v.z, v.w);
        *(uint2*)(jb.dst + (size_t)i * 4) = make_uint2(*(unsigned*)&a, *(unsigned*)&b);
    }
}

// =====================================================================
// fp16 x1 tensor-core NT GEMM, cp.async double-buffered (unchanged R14).
// =====================================================================
struct GemmJob {
    const __half* A; const __half* W; const float* bias;
    float* C; __half* Ch;
    int M; int mode;
};
struct GemmJobs { GemmJob j[4]; };

__global__ void __launch_bounds__(256) gemm_f16(GemmJobs jobs)
{
    __shared__ __half gsm[20480];

    const GemmJob job = jobs.j[blockIdx.z];
    const int M = job.M;
    const int m0 = blockIdx.y * 128;
    if (m0 >= M) return;
    const int n0 = blockIdx.x * 128;

    const int tid = threadIdx.x, lane = tid & 31, warp = tid >> 5;
    const int wm = warp & 1, wn = warp >> 1;
    const int arow = lane & 15;
    const int asel = (lane >> 4) << 3;
    const int bn_off = lane & 7;
    const int bsel = ((lane >> 3) & 1) << 3;

    float acc[4][4][4];
#pragma unroll
    for (int i = 0; i < 4; i++)
#pragma unroll
        for (int j = 0; j < 4; j++)
#pragma unroll
            for (int q = 0; q < 4; q++) acc[i][j][q] = 0.f;

#define STAGE(s) do {                                                        \
        int _buf = (s) & 1, _k0 = (s) * 32;                                  \
        _Pragma("unroll")                                                    \
        for (int _t = 0; _t < 4; _t++) {                                     \
            int _i = tid + _t * 256;                                         \
            int _isW = _i >> 9, _j = _i & 511;                               \
            int _r = _j >> 2, _cc = (_j & 3) << 3;                           \
            const __half* _src;                                              \
            if (_isW) {                                                      \
                _src = job.W + (size_t)(n0 + _r) * 512 + _k0 + _cc;          \
            } else {                                                         \
                int _gm = m0 + _r; if (_gm >= M) _gm = M - 1;                \
                _src = job.A + (size_t)_gm * 512 + _k0 + _cc;                \
            }                                                                \
            cp16(&gsm[_buf * 10240 + _isW * 5120 + _r * 40 + _cc], _src);    \
        }                                                                    \
        asm volatile("cp.async.commit_group;");                              \
    } while (0)

    STAGE(0);

    for (int s = 0; s < 16; s++) {
        if (s < 15) {
            STAGE(s + 1);
            asm volatile("cp.async.wait_group 1;" ::: "memory");
        } else {
            asm volatile("cp.async.wait_group 0;" ::: "memory");
        }
        __syncthreads();
        const __half* SA = gsm + (s & 1) * 10240;
        const __half* SW = SA + 5120;

#pragma unroll
        for (int kk = 0; kk < 2; kk++) {
            const int kb = kk << 4;
            unsigned ah[4][4], bh[4][2];
#pragma unroll
            for (int i = 0; i < 4; i++) {
                int r = wm * 64 + i * 16 + arow;
                ldsm_x4(smem_u32(&SA[r * 40 + kb + asel]),
                        ah[i][0], ah[i][1], ah[i][2], ah[i][3]);
            }
#pragma unroll
            for (int j = 0; j < 4; j++) {
                int n = wn * 32 + j * 8 + bn_off;
                ldsm_x2(smem_u32(&SW[n * 40 + kb + bsel]), bh[j][0], bh[j][1]);
            }
#pragma unroll
            for (int i = 0; i < 4; i++)
#pragma unroll
                for (int j = 0; j < 4; j++)
                    mma_fp16(acc[i][j][0], acc[i][j][1], acc[i][j][2], acc[i][j][3],
                             ah[i][0], ah[i][1], ah[i][2], ah[i][3], bh[j][0], bh[j][1]);
        }
        __syncthreads();
    }
#undef STAGE

#pragma unroll
    for (int i = 0; i < 4; i++) {
        int mbase = m0 + wm * 64 + i * 16 + (lane >> 2);
#pragma unroll
        for (int j = 0; j < 4; j++) {
            int n = n0 + wn * 32 + j * 8 + (lane & 3) * 2;
            float bb0 = job.bias ? job.bias[n] : 0.f;
            float bb1 = job.bias ? job.bias[n + 1] : 0.f;
#pragma unroll
            for (int half = 0; half < 2; half++) {
                int m = mbase + half * 8;
                if (m >= M) continue;
                float v0 = acc[i][j][half * 2 + 0] + bb0;
                float v1 = acc[i][j][half * 2 + 1] + bb1;
                if (job.mode == 0) {
                    job.C[(size_t)m * 512 + n] = v0;
                    job.C[(size_t)m * 512 + n + 1] = v1;
                } else if (job.mode == 1) {
                    __half2 hv = __floats2half2_rn(v0, v1);
                    *(__half2*)(job.Ch + (size_t)m * 512 + n) = hv;
                } else {
                    int bb = m >> 10, ss = m & 1023;
#pragma unroll
                    for (int e = 0; e < 2; e++) {
                        int nn = n + e;
                        int hh = nn >> 6, dd = nn & 63;
                        size_t dst = (((size_t)(bb * H_ + hh) * DK_ + dd) * T_ + ss);
                        job.Ch[dst] = __float2half(e ? v1 : v0);
                    }
                }
            }
        }
    }
}

// =====================================================================
// Fused flash attention: 128 t-rows / 4 warps (2 strips per warp),
// grid (8, B*H), 96.5KB smem -> 2 CTAs/SM. Shared V-fragment loads
// across strips; per-strip G/S/softmax identical to R14 constants.
// =====================================================================
#define FL_SMEM 96512

__global__ void __launch_bounds__(128) flash_kernel(
    const float* __restrict__ pu, const float* __restrict__ pv,
    const int* __restrict__ mask)
{
    extern __shared__ char sm[];
    __half* KF = (__half*)(sm);                           // 2 x [64][72]
    __half* VF = (__half*)(sm + 18432);                   // 2 x [64 d][72 s]
    __half* PF = (__half*)(sm + 36864);                   // [256][72] circular
    float* GS  = (float*)(sm + 73728);                    // [4 warps][16][88]
    float* MSK = (float*)(sm + 96256);                    // [64]
    // prologue aliases over the PF region (dead before first P prefetch)
    __half* QUF = (__half*)(sm + 36864);                  // [128][72]
    __half* QVF = (__half*)(sm + 55296);

    const int tid = threadIdx.x, lane = tid & 31, warp = tid >> 5;
    const int gid = lane >> 2, tig = lane & 3;
    const int bh = blockIdx.y, b = bh >> 3, h = bh & 7;
    const int t0 = blockIdx.x * 128;
    const int pbase0 = T_ - 1 - t0 - 127;   // >= 0

    // ---- phase 0: qu/qv fp16 staging for 128 rows (scaled by 0.125) ----
    for (int x = tid; x < 2048; x += 128) {
        int r = x >> 4, c = (x & 15) << 2;
        uint2 qraw = *(const uint2*)(g_Qf + ((size_t)(b * T_ + t0 + r)) * F_ + h * DK_ + c);
        __half2 q01 = *(__half2*)&qraw.x;
        __half2 q23 = *(__half2*)&qraw.y;
        float qs[4] = {__low2float(q01), __high2float(q01),
                       __low2float(q23), __high2float(q23)};
        float4 u4 = *(const float4*)(pu + h * DK_ + c);
        float4 v4 = *(const float4*)(pv + h * DK_ + c);
        float us[4] = {u4.x, u4.y, u4.z, u4.w};
        float vs[4] = {v4.x, v4.y, v4.z, v4.w};
#pragma unroll
        for (int e = 0; e < 4; e++) {
            QUF[r * 72 + c + e] = __float2half((qs[e] + us[e]) * 0.125f);
            QVF[r * 72 + c + e] = __float2half((qs[e] + vs[e]) * 0.125f);
        }
    }
    __syncthreads();

    // per-warp: two 16-row strips (st = warp*2 + ss)
    unsigned quf[2][4][4], qvf[2][4][4];
#pragma unroll
    for (int ss = 0; ss < 2; ss++) {
        int ar = (warp * 2 + ss) * 16 + (lane & 15);
        int ac = (lane >> 4) << 3;
#pragma unroll
        for (int kc = 0; kc < 4; kc++) {
            ldsm_x4(smem_u32(&QUF[ar * 72 + kc * 16 + ac]),
                    quf[ss][kc][0], quf[ss][kc][1], quf[ss][kc][2], quf[ss][kc][3]);
            ldsm_x4(smem_u32(&QVF[ar * 72 + kc * 16 + ac]),
                    qvf[ss][kc][0], qvf[ss][kc][1], qvf[ss][kc][2], qvf[ss][kc][3]);
        }
    }
    __syncthreads();   // PF region free from here on

    // ---- initial prefetch: tile 0 K/V (buf 0) + P rows [0,192) ----
    for (int x = tid; x < 512; x += 128) {
        int r = x >> 3, c = (x & 7) << 3;
        size_t ksrc = ((size_t)(b * T_ + r)) * F_ + h * DK_ + c;
        cp16(&KF[r * 72 + c], g_Kf + ksrc);
        size_t vsrc = ((size_t)bh * DK_ + r) * T_ + c;
        cp16(&VF[r * 72 + c], g_Vf + vsrc);
    }
    for (int x = tid; x < 1536; x += 128) {
        int rr = x >> 3, c = (x & 7) << 3;
        int grow = pbase0 + rr; if (grow > P_) grow = P_;
        cp16(&PF[rr * 72 + c], g_Pf + (size_t)grow * F_ + h * DK_ + c);
    }
    asm volatile("cp.async.commit_group;");

    float o[2][8][4];
#pragma unroll
    for (int ss = 0; ss < 2; ss++)
#pragma unroll
        for (int nt = 0; nt < 8; nt++)
#pragma unroll
            for (int q = 0; q < 4; q++) o[ss][nt][q] = 0.f;
    float mr[2][2], lsum[2][2];
#pragma unroll
    for (int ss = 0; ss < 2; ss++) {
        mr[ss][0] = -1e30f; mr[ss][1] = -1e30f;
        lsum[ss][0] = 0.f;  lsum[ss][1] = 0.f;
    }
    float* GSw = GS + warp * (16 * 88);

    for (int i = 0; i < 16; i++) {
        const int s0 = i * 64;

        // ---- prefetch tile i+1 (K/V buf flip + 64 new P rows) ----
        if (i < 15) {
            __half* kf = KF + ((i + 1) & 1) * 4608;
            __half* vf = VF + ((i + 1) & 1) * 4608;
            int s0n = s0 + 64;
            for (int x = tid; x < 512; x += 128) {
                int r = x >> 3, c = (x & 7) << 3;
                size_t ksrc = ((size_t)(b * T_ + s0n + r)) * F_ + h * DK_ + c;
                cp16(&kf[r * 72 + c], g_Kf + ksrc);
                size_t vsrc = ((size_t)bh * DK_ + r) * T_ + s0n + c;
                cp16(&vf[r * 72 + c], g_Vf + vsrc);
            }
            int u0 = 192 + 64 * i;
            for (int x = tid; x < 512; x += 128) {
                int rr = x >> 3, c = (x & 7) << 3;
                int un = u0 + rr;
                int slot = un & 255;
                int grow = pbase0 + un; if (grow > P_) grow = P_;
                cp16(&PF[slot * 72 + c], g_Pf + (size_t)grow * F_ + h * DK_ + c);
            }
            asm volatile("cp.async.commit_group;");
        }
        if (tid < 64) MSK[tid] = (mask[b * T_ + s0 + tid] == 0) ? -3.0e38f : 0.f;
        if (i < 15) asm volatile("cp.async.wait_group 1;" ::: "memory");
        else        asm volatile("cp.async.wait_group 0;" ::: "memory");
        __syncthreads();

        const __half* kf = KF + (i & 1) * 4608;
        const __half* vf = VF + (i & 1) * 4608;
        const int off = (64 * i) & 255;

        unsigned af[2][4][4];   // packed probabilities per strip per kc

#pragma unroll
        for (int ss = 0; ss < 2; ss++) {
            const int st = warp * 2 + ss;

            // ---- G = qv_strip @ Pwin^T (banded BD, fp16, 2 chains) ----
            {
                int prow = 112 - 16 * st + (lane & 7);
                int psel = ((lane >> 3) & 1) << 3;
#pragma unroll
                for (int nt = 0; nt < 10; nt++) {
                    float gA0 = 0.f, gA1 = 0.f, gA2 = 0.f, gA3 = 0.f;
                    float gB0 = 0.f, gB1 = 0.f, gB2 = 0.f, gB3 = 0.f;
                    int prw = (prow + nt * 8 + off) & 255;
#pragma unroll
                    for (int kc = 0; kc < 4; kc += 2) {
                        unsigned p0, p1, p2, p3;
                        ldsm_x2(smem_u32(&PF[prw * 72 + kc * 16 + psel]), p0, p1);
                        ldsm_x2(smem_u32(&PF[prw * 72 + (kc + 1) * 16 + psel]), p2, p3);
                        mma_fp16(gA0, gA1, gA2, gA3,
                                 qvf[ss][kc][0], qvf[ss][kc][1], qvf[ss][kc][2], qvf[ss][kc][3], p0, p1);
                        mma_fp16(gB0, gB1, gB2, gB3,
                                 qvf[ss][kc + 1][0], qvf[ss][kc + 1][1], qvf[ss][kc + 1][2], qvf[ss][kc + 1][3], p2, p3);
                    }
                    int gc = nt * 8 + 2 * tig;
                    GSw[gid * 88 + gc] = gA0 + gB0;
                    GSw[gid * 88 + gc + 1] = gA1 + gB1;
                    GSw[(gid + 8) * 88 + gc] = gA2 + gB2;
                    GSw[(gid + 8) * 88 + gc + 1] = gA3 + gB3;
                }
            }
            __syncwarp();

            // ---- S = qu @ K^T + band(G) + mask (fp16, 2 chains) ----
            float sf[8][4];
            {
                int krow = lane & 7;
                int ksel = ((lane >> 3) & 1) << 3;
#pragma unroll
                for (int nt = 0; nt < 8; nt++) {
                    float aA0 = 0.f, aA1 = 0.f, aA2 = 0.f, aA3 = 0.f;
                    float aB0 = 0.f, aB1 = 0.f, aB2 = 0.f, aB3 = 0.f;
#pragma unroll
                    for (int kc = 0; kc < 4; kc += 2) {
                        unsigned k0, k1, k2, k3;
                        ldsm_x2(smem_u32(&kf[(nt * 8 + krow) * 72 + kc * 16 + ksel]), k0, k1);
                        ldsm_x2(smem_u32(&kf[(nt * 8 + krow) * 72 + (kc + 1) * 16 + ksel]), k2, k3);
                        mma_fp16(aA0, aA1, aA2, aA3,
                                 quf[ss][kc][0], quf[ss][kc][1], quf[ss][kc][2], quf[ss][kc][3], k0, k1);
                        mma_fp16(aB0, aB1, aB2, aB3,
                                 quf[ss][kc + 1][0], quf[ss][kc + 1][1], quf[ss][kc + 1][2], quf[ss][kc + 1][3], k2, k3);
                    }
                    int col = nt * 8 + 2 * tig;
                    sf[nt][0] = aA0 + aB0 + GSw[gid * 88 + col - gid + 15] + MSK[col];
                    sf[nt][1] = aA1 + aB1 + GSw[gid * 88 + col - gid + 16] + MSK[col + 1];
                    sf[nt][2] = aA2 + aB2 + GSw[(gid + 8) * 88 + col - gid + 7] + MSK[col];
                    sf[nt][3] = aA3 + aB3 + GSw[(gid + 8) * 88 + col - gid + 8] + MSK[col + 1];
                }
            }

            // ---- online softmax (strip ss) ----
            float mx0 = -1e30f, mx1 = -1e30f;
#pragma unroll
            for (int nt = 0; nt < 8; nt++) {
                mx0 = fmaxf(mx0, fmaxf(sf[nt][0], sf[nt][1]));
                mx1 = fmaxf(mx1, fmaxf(sf[nt][2], sf[nt][3]));
            }
            mx0 = fmaxf(mx0, __shfl_xor_sync(0xffffffffu, mx0, 1));
            mx0 = fmaxf(mx0, __shfl_xor_sync(0xffffffffu, mx0, 2));
            mx1 = fmaxf(mx1, __shfl_xor_sync(0xffffffffu, mx1, 1));
            mx1 = fmaxf(mx1, __shfl_xor_sync(0xffffffffu, mx1, 2));
            float mn0 = fmaxf(mr[ss][0], mx0), mn1 = fmaxf(mr[ss][1], mx1);
            float sc0 = __expf(mr[ss][0] - mn0), sc1 = __expf(mr[ss][1] - mn1);
            float su0 = 0.f, su1 = 0.f;
#pragma unroll
            for (int nt = 0; nt < 8; nt++) {
                sf[nt][0] = __expf(sf[nt][0] - mn0);
                sf[nt][1] = __expf(sf[nt][1] - mn0);
                sf[nt][2] = __expf(sf[nt][2] - mn1);
                sf[nt][3] = __expf(sf[nt][3] - mn1);
                su0 += sf[nt][0] + sf[nt][1];
                su1 += sf[nt][2] + sf[nt][3];
            }
            su0 += __shfl_xor_sync(0xffffffffu, su0, 1);
            su0 += __shfl_xor_sync(0xffffffffu, su0, 2);
            su1 += __shfl_xor_sync(0xffffffffu, su1, 1);
            su1 += __shfl_xor_sync(0xffffffffu, su1, 2);
            lsum[ss][0] = lsum[ss][0] * sc0 + su0;
            lsum[ss][1] = lsum[ss][1] * sc1 + su1;
            mr[ss][0] = mn0; mr[ss][1] = mn1;
#pragma unroll
            for (int nt = 0; nt < 8; nt++) {
                o[ss][nt][0] *= sc0; o[ss][nt][1] *= sc0;
                o[ss][nt][2] *= sc1; o[ss][nt][3] *= sc1;
            }
            // pack probabilities to fp16 fragments
#pragma unroll
            for (int kc = 0; kc < 4; kc++) {
                pack_f16(sf[2 * kc][0], sf[2 * kc][1], af[ss][kc][0]);
                pack_f16(sf[2 * kc][2], sf[2 * kc][3], af[ss][kc][1]);
                pack_f16(sf[2 * kc + 1][0], sf[2 * kc + 1][1], af[ss][kc][2]);
                pack_f16(sf[2 * kc + 1][2], sf[2 * kc + 1][3], af[ss][kc][3]);
            }
        }

        // ---- O += P @ V: V fragments loaded ONCE, feed both strips ----
        {
            int vrow = lane & 7;
            int vsel = ((lane >> 3) & 1) << 3;
#pragma unroll
            for (int kc = 0; kc < 4; kc++) {
#pragma unroll
                for (int nt = 0; nt < 8; nt++) {
                    unsigned v0, v1;
                    ldsm_x2(smem_u32(&vf[(nt * 8 + vrow) * 72 + kc * 16 + vsel]), v0, v1);
                    mma_fp16(o[0][nt][0], o[0][nt][1], o[0][nt][2], o[0][nt][3],
                             af[0][kc][0], af[0][kc][1], af[0][kc][2], af[0][kc][3], v0, v1);
                    mma_fp16(o[1][nt][0], o[1][nt][1], o[1][nt][2], o[1][nt][3],
                             af[1][kc][0], af[1][kc][1], af[1][kc][2], af[1][kc][3], v0, v1);
                }
            }
        }
        __syncthreads();
    }

    // ---- epilogue: write ctx fp16 (both strips) ----
#pragma unroll
    for (int ss = 0; ss < 2; ss++) {
        float inv0 = (lsum[ss][0] > 0.f) ? 1.f / lsum[ss][0] : 0.f;
        float inv1 = (lsum[ss][1] > 0.f) ? 1.f / lsum[ss][1] : 0.f;
        int row0 = t0 + (warp * 2 + ss) * 16 + gid;
#pragma unroll
        for (int nt = 0; nt < 8; nt++) {
            int colg = h * DK_ + nt * 8 + 2 * tig;
            __half2 w0 = __floats2half2_rn(o[ss][nt][0] * inv0, o[ss][nt][1] * inv0);
            *(__half2*)&g_Cf[((size_t)(b * T_ + row0)) * F_ + colg] = w0;
            __half2 w1 = __floats2half2_rn(o[ss][nt][2] * inv1, o[ss][nt][3] * inv1);
            *(__half2*)&g_Cf[((size_t)(b * T_ + row0 + 8)) * F_ + colg] = w1;
        }
    }
}

// =====================================================================
extern "C" void kernel_launch(void* const* d_in, const int* in_sizes, int n_in,
                              void* d_out, int out_size)
{
    const float* query   = (const float*)d_in[0];
    const float* key_in  = (const float*)d_in[1];
    const float* value   = (const float*)d_in[2];
    const float* pos_emb = (const float*)d_in[3];
    const int*   mask    = (const int*)d_in[4];
    const float* Wq = (const float*)d_in[5];
    const float* bq = (const float*)d_in[6];
    const float* Wk = (const float*)d_in[7];
    const float* bk = (const float*)d_in[8];
    const float* Wv = (const float*)d_in[9];
    const float* bv = (const float*)d_in[10];
    const float* Wo = (const float*)d_in[11];
    const float* bo = (const float*)d_in[12];
    const float* Wp = (const float*)d_in[13];
    const float* pu = (const float*)d_in[14];
    const float* pv = (const float*)d_in[15];
    float* out = (float*)d_out;

    __half *Xq, *Xk, *Xv, *Xp, *Wqf, *Wkf, *Wvf, *Wpf, *Wof;
    __half *Qfp, *Kfp, *Vfp, *Pfp, *Cfp;
    cudaGetSymbolAddress((void**)&Xq,  g_Xq);
    cudaGetSymbolAddress((void**)&Xk,  g_Xk);
    cudaGetSymbolAddress((void**)&Xv,  g_Xv);
    cudaGetSymbolAddress((void**)&Xp,  g_Xp);
    cudaGetSymbolAddress((void**)&Wqf, g_Wq);
    cudaGetSymbolAddress((void**)&Wkf, g_Wk);
    cudaGetSymbolAddress((void**)&Wvf, g_Wv);
    cudaGetSymbolAddress((void**)&Wpf, g_Wp);
    cudaGetSymbolAddress((void**)&Wof, g_Wo);
    cudaGetSymbolAddress((void**)&Qfp, g_Qf);
    cudaGetSymbolAddress((void**)&Kfp, g_Kf);
    cudaGetSymbolAddress((void**)&Vfp, g_Vf);
    cudaGetSymbolAddress((void**)&Pfp, g_Pf);
    cudaGetSymbolAddress((void**)&Cfp, g_Cf);

    cudaFuncSetAttribute(flash_kernel, cudaFuncAttributeMaxDynamicSharedMemorySize, FL_SMEM);

    // ---- prepass: fp32 -> fp16 for all GEMM operands ----
    const int NBT = B_ * T_ * F_ / 4;
    const int NP  = P_ * F_ / 4;
    const int NW  = F_ * F_ / 4;
    CvtJobs cj;
    cj.j[0] = { query,   Xq,  NBT };
    cj.j[1] = { key_in,  Xk,  NBT };
    cj.j[2] = { value,   Xv,  NBT };
    cj.j[3] = { pos_emb, Xp,  NP  };
    cj.j[4] = { Wq, Wqf, NW };
    cj.j[5] = { Wk, Wkf, NW };
    cj.j[6] = { Wv, Wvf, NW };
    cj.j[7] = { Wp, Wpf, NW };
    cj.j[8] = { Wo, Wof, NW };
    cvt_f16<<<dim3(256, 9), 256>>>(cj);

    // ---- all 4 input projections in ONE launch (fp16 x1, cp.async) ----
    GemmJobs pj;
    pj.j[0] = { Xq, Wqf, bq,      nullptr, Qfp, B_ * T_, 1 };
    pj.j[1] = { Xk, Wkf, bk,      nullptr, Kfp, B_ * T_, 1 };
    pj.j[2] = { Xv, Wvf, bv,      nullptr, Vfp, B_ * T_, 2 };
    pj.j[3] = { Xp, Wpf, nullptr, nullptr, Pfp, P_,      1 };
    gemm_f16<<<dim3(4, 64, 4), 256>>>(pj);

    // fused attention (fp16, 2 strips/warp, 2 CTAs/SM)
    flash_kernel<<<dim3(8, B_ * H_), 128, FL_SMEM>>>(pu, pv, mask);

    // output projection (fp16 x1, fp32 out)
    GemmJobs oj;
    oj.j[0] = { Cfp, Wof, bo, out, nullptr, B_ * T_, 0 };
    oj.j[1] = oj.j[0]; oj.j[2] = oj.j[0]; oj.j[3] = oj.j[0];
    gemm_f16<<<dim3(4, 64, 1), 256>>>(oj);
}

// round 17
// speedup vs baseline: 2.0220x; 1.0883x over previous
#include <cuda_runtime.h>
#include <cuda_bf16.h>
#include <cuda_fp16.h>
#include <math.h>

#define B_ 8
#define T_ 1024
#define F_ 512
#define H_ 8
#define DK_ 64
#define P_ 2047

// -------- scratch (device globals; no allocations allowed) --------
__device__ __half g_Xq[(size_t)B_ * T_ * F_];   // fp16 inputs (prepass)
__device__ __half g_Xk[(size_t)B_ * T_ * F_];
__device__ __half g_Xv[(size_t)B_ * T_ * F_];
__device__ __half g_Xp[(size_t)2048 * F_];
__device__ __half g_Wq[(size_t)F_ * F_];        // fp16 weights (prepass)
__device__ __half g_Wk[(size_t)F_ * F_];
__device__ __half g_Wv[(size_t)F_ * F_];
__device__ __half g_Wp[(size_t)F_ * F_];
__device__ __half g_Wo[(size_t)F_ * F_];
__device__ __half g_Qf[(size_t)B_ * T_ * F_];   // q proj (fp16)
__device__ __half g_Kf[(size_t)B_ * T_ * F_];   // k proj (fp16)
__device__ __half g_Vf[(size_t)B_ * H_ * DK_ * T_]; // v^T fp16 [b,h,d,s]
__device__ __half g_Pf[(size_t)(P_ + 1) * F_];  // p proj (fp16, row 2047 = 0)
__device__ __half g_Cf[(size_t)B_ * T_ * F_];   // ctx fp16 (flash out)

// =====================================================================
// Helpers
// =====================================================================
__device__ __forceinline__ unsigned smem_u32(const void* p) {
    return (unsigned)__cvta_generic_to_shared(p);
}
__device__ __forceinline__ void ldsm_x4(unsigned addr, unsigned& r0, unsigned& r1,
                                        unsigned& r2, unsigned& r3) {
    asm volatile("ldmatrix.sync.aligned.m8n8.x4.shared.b16 {%0,%1,%2,%3}, [%4];"
                 : "=r"(r0), "=r"(r1), "=r"(r2), "=r"(r3) : "r"(addr));
}
__device__ __forceinline__ void ldsm_x2(unsigned addr, unsigned& r0, unsigned& r1) {
    asm volatile("ldmatrix.sync.aligned.m8n8.x2.shared.b16 {%0,%1}, [%2];"
                 : "=r"(r0), "=r"(r1) : "r"(addr));
}
__device__ __forceinline__ void mma_fp16(float& c0, float& c1, float& c2, float& c3,
                                         unsigned a0, unsigned a1, unsigned a2, unsigned a3,
                                         unsigned b0, unsigned b1) {
    asm volatile(
        "mma.sync.aligned.m16n8k16.row.col.f32.f16.f16.f32 "
        "{%0,%1,%2,%3},{%4,%5,%6,%7},{%8,%9},{%0,%1,%2,%3};"
        : "+f"(c0), "+f"(c1), "+f"(c2), "+f"(c3)
        : "r"(a0), "r"(a1), "r"(a2), "r"(a3), "r"(b0), "r"(b1));
}
__device__ __forceinline__ void pack_f16(float x0, float x1, unsigned& r) {
    __half2 h = __floats2half2_rn(x0, x1);
    r = *(unsigned*)&h;
}
__device__ __forceinline__ void cp16(void* smem_dst, const void* gsrc) {
    unsigned d = smem_u32(smem_dst);
    asm volatile("cp.async.cg.shared.global [%0], [%1], 16;" :: "r"(d), "l"(gsrc));
}

// =====================================================================
// Prepass: fp32 -> fp16 conversion (4 inputs + 5 weights)
// =====================================================================
struct CvtJob { const float* src; __half* dst; int n4; };
struct CvtJobs { CvtJob j[9]; };

__global__ void __launch_bounds__(256) cvt_f16(CvtJobs jobs)
{
    const CvtJob jb = jobs.j[blockIdx.y];
    const int stride = gridDim.x * blockDim.x;
    for (int i = blockIdx.x * blockDim.x + threadIdx.x; i < jb.n4; i += stride) {
        float4 v = ((const float4*)jb.src)[i];
        __half2 a = __floats2half2_rn(v.x, v.y);
        __half2 b = __floats2half2_rn(v.z, v.w);
        *(uint2*)(jb.dst + (size_t)i * 4) = make_uint2(*(unsigned*)&a, *(unsigned*)&b);
    }
}

// =====================================================================
// fp16 x1 tensor-core NT GEMM, cp.async TRIPLE-buffered, multi-job.
// 61.4KB dynamic smem. Same 128x128 / 8-warp / 64x32 geometry.
// =====================================================================
#define G16_SMEM 61440

struct GemmJob {
    const __half* A; const __half* W; const float* bias;
    float* C; __half* Ch;
    int M; int mode;
};
struct GemmJobs { GemmJob j[4]; };

__global__ void __launch_bounds__(256) gemm_f16(GemmJobs jobs)
{
    extern __shared__ __half gsm[];   // 3 bufs x (A 5120 + W 5120)

    const GemmJob job = jobs.j[blockIdx.z];
    const int M = job.M;
    const int m0 = blockIdx.y * 128;
    if (m0 >= M) return;
    const int n0 = blockIdx.x * 128;

    const int tid = threadIdx.x, lane = tid & 31, warp = tid >> 5;
    const int wm = warp & 1, wn = warp >> 1;
    const int arow = lane & 15;
    const int asel = (lane >> 4) << 3;
    const int bn_off = lane & 7;
    const int bsel = ((lane >> 3) & 1) << 3;

    float acc[4][4][4];
#pragma unroll
    for (int i = 0; i < 4; i++)
#pragma unroll
        for (int j = 0; j < 4; j++)
#pragma unroll
            for (int q = 0; q < 4; q++) acc[i][j][q] = 0.f;

#define STAGE(s) do {                                                        \
        int _buf = (s) % 3, _k0 = (s) * 32;                                  \
        _Pragma("unroll")                                                    \
        for (int _t = 0; _t < 4; _t++) {                                     \
            int _i = tid + _t * 256;                                         \
            int _isW = _i >> 9, _j = _i & 511;                               \
            int _r = _j >> 2, _cc = (_j & 3) << 3;                           \
            const __half* _src;                                              \
            if (_isW) {                                                      \
                _src = job.W + (size_t)(n0 + _r) * 512 + _k0 + _cc;          \
            } else {                                                         \
                int _gm = m0 + _r; if (_gm >= M) _gm = M - 1;                \
                _src = job.A + (size_t)_gm * 512 + _k0 + _cc;                \
            }                                                                \
            cp16(&gsm[_buf * 10240 + _isW * 5120 + _r * 40 + _cc], _src);    \
        }                                                                    \
        asm volatile("cp.async.commit_group;");                              \
    } while (0)

    STAGE(0);
    STAGE(1);

    for (int s = 0; s < 16; s++) {
        if (s <= 13) {
            STAGE(s + 2);
            asm volatile("cp.async.wait_group 2;" ::: "memory");
        } else if (s == 14) {
            asm volatile("cp.async.wait_group 1;" ::: "memory");
        } else {
            asm volatile("cp.async.wait_group 0;" ::: "memory");
        }
        __syncthreads();
        const __half* SA = gsm + (s % 3) * 10240;
        const __half* SW = SA + 5120;

#pragma unroll
        for (int kk = 0; kk < 2; kk++) {
            const int kb = kk << 4;
            unsigned ah[4][4], bh[4][2];
#pragma unroll
            for (int i = 0; i < 4; i++) {
                int r = wm * 64 + i * 16 + arow;
                ldsm_x4(smem_u32(&SA[r * 40 + kb + asel]),
                        ah[i][0], ah[i][1], ah[i][2], ah[i][3]);
            }
#pragma unroll
            for (int j = 0; j < 4; j++) {
                int n = wn * 32 + j * 8 + bn_off;
                ldsm_x2(smem_u32(&SW[n * 40 + kb + bsel]), bh[j][0], bh[j][1]);
            }
#pragma unroll
            for (int i = 0; i < 4; i++)
#pragma unroll
                for (int j = 0; j < 4; j++)
                    mma_fp16(acc[i][j][0], acc[i][j][1], acc[i][j][2], acc[i][j][3],
                             ah[i][0], ah[i][1], ah[i][2], ah[i][3], bh[j][0], bh[j][1]);
        }
        __syncthreads();
    }
#undef STAGE

#pragma unroll
    for (int i = 0; i < 4; i++) {
        int mbase = m0 + wm * 64 + i * 16 + (lane >> 2);
#pragma unroll
        for (int j = 0; j < 4; j++) {
            int n = n0 + wn * 32 + j * 8 + (lane & 3) * 2;
            float bb0 = job.bias ? job.bias[n] : 0.f;
            float bb1 = job.bias ? job.bias[n + 1] : 0.f;
#pragma unroll
            for (int half = 0; half < 2; half++) {
                int m = mbase + half * 8;
                if (m >= M) continue;
                float v0 = acc[i][j][half * 2 + 0] + bb0;
                float v1 = acc[i][j][half * 2 + 1] + bb1;
                if (job.mode == 0) {
                    job.C[(size_t)m * 512 + n] = v0;
                    job.C[(size_t)m * 512 + n + 1] = v1;
                } else if (job.mode == 1) {
                    __half2 hv = __floats2half2_rn(v0, v1);
                    *(__half2*)(job.Ch + (size_t)m * 512 + n) = hv;
                } else {
                    int bb = m >> 10, ss = m & 1023;
#pragma unroll
                    for (int e = 0; e < 2; e++) {
                        int nn = n + e;
                        int hh = nn >> 6, dd = nn & 63;
                        size_t dst = (((size_t)(bb * H_ + hh) * DK_ + dd) * T_ + ss);
                        job.Ch[dst] = __float2half(e ? v1 : v0);
                    }
                }
            }
        }
    }
}

// =====================================================================
// Fused flash attention: 128 t-rows / 4 warps (2 strips per warp),
// grid (8, B*H), 96.5KB smem -> 2 CTAs/SM. Shared K AND V fragment
// loads across strips; band+mask preloaded into S accumulators.
// =====================================================================
#define FL_SMEM 96512

__global__ void __launch_bounds__(128) flash_kernel(
    const float* __restrict__ pu, const float* __restrict__ pv,
    const int* __restrict__ mask)
{
    extern __shared__ char sm[];
    __half* KF = (__half*)(sm);                           // 2 x [64][72]
    __half* VF = (__half*)(sm + 18432);                   // 2 x [64 d][72 s]
    __half* PF = (__half*)(sm + 36864);                   // [256][72] circular
    float* GS  = (float*)(sm + 73728);                    // [4 warps][16][88]
    float* MSK = (float*)(sm + 96256);                    // [64]
    // prologue aliases over the PF region (dead before first P prefetch)
    __half* QUF = (__half*)(sm + 36864);                  // [128][72]
    __half* QVF = (__half*)(sm + 55296);

    const int tid = threadIdx.x, lane = tid & 31, warp = tid >> 5;
    const int gid = lane >> 2, tig = lane & 3;
    const int bh = blockIdx.y, b = bh >> 3, h = bh & 7;
    const int t0 = blockIdx.x * 128;
    const int pbase0 = T_ - 1 - t0 - 127;   // >= 0

    // ---- phase 0: qu/qv fp16 staging for 128 rows (scaled by 0.125) ----
    for (int x = tid; x < 2048; x += 128) {
        int r = x >> 4, c = (x & 15) << 2;
        uint2 qraw = *(const uint2*)(g_Qf + ((size_t)(b * T_ + t0 + r)) * F_ + h * DK_ + c);
        __half2 q01 = *(__half2*)&qraw.x;
        __half2 q23 = *(__half2*)&qraw.y;
        float qs[4] = {__low2float(q01), __high2float(q01),
                       __low2float(q23), __high2float(q23)};
        float4 u4 = *(const float4*)(pu + h * DK_ + c);
        float4 v4 = *(const float4*)(pv + h * DK_ + c);
        float us[4] = {u4.x, u4.y, u4.z, u4.w};
        float vs[4] = {v4.x, v4.y, v4.z, v4.w};
#pragma unroll
        for (int e = 0; e < 4; e++) {
            QUF[r * 72 + c + e] = __float2half((qs[e] + us[e]) * 0.125f);
            QVF[r * 72 + c + e] = __float2half((qs[e] + vs[e]) * 0.125f);
        }
    }
    __syncthreads();

    // per-warp: two 16-row strips (st = warp*2 + ss)
    unsigned quf[2][4][4], qvf[2][4][4];
#pragma unroll
    for (int ss = 0; ss < 2; ss++) {
        int ar = (warp * 2 + ss) * 16 + (lane & 15);
        int ac = (lane >> 4) << 3;
#pragma unroll
        for (int kc = 0; kc < 4; kc++) {
            ldsm_x4(smem_u32(&QUF[ar * 72 + kc * 16 + ac]),
                    quf[ss][kc][0], quf[ss][kc][1], quf[ss][kc][2], quf[ss][kc][3]);
            ldsm_x4(smem_u32(&QVF[ar * 72 + kc * 16 + ac]),
                    qvf[ss][kc][0], qvf[ss][kc][1], qvf[ss][kc][2], qvf[ss][kc][3]);
        }
    }
    __syncthreads();   // PF region free from here on

    // ---- initial prefetch: tile 0 K/V (buf 0) + P rows [0,192) ----
    for (int x = tid; x < 512; x += 128) {
        int r = x >> 3, c = (x & 7) << 3;
        size_t ksrc = ((size_t)(b * T_ + r)) * F_ + h * DK_ + c;
        cp16(&KF[r * 72 + c], g_Kf + ksrc);
        size_t vsrc = ((size_t)bh * DK_ + r) * T_ + c;
        cp16(&VF[r * 72 + c], g_Vf + vsrc);
    }
    for (int x = tid; x < 1536; x += 128) {
        int rr = x >> 3, c = (x & 7) << 3;
        int grow = pbase0 + rr; if (grow > P_) grow = P_;
        cp16(&PF[rr * 72 + c], g_Pf + (size_t)grow * F_ + h * DK_ + c);
    }
    asm volatile("cp.async.commit_group;");

    float o[2][8][4];
#pragma unroll
    for (int ss = 0; ss < 2; ss++)
#pragma unroll
        for (int nt = 0; nt < 8; nt++)
#pragma unroll
            for (int q = 0; q < 4; q++) o[ss][nt][q] = 0.f;
    float mr[2][2], lsum[2][2];
#pragma unroll
    for (int ss = 0; ss < 2; ss++) {
        mr[ss][0] = -1e30f; mr[ss][1] = -1e30f;
        lsum[ss][0] = 0.f;  lsum[ss][1] = 0.f;
    }
    float* GSw = GS + warp * (16 * 88);

    for (int i = 0; i < 16; i++) {
        const int s0 = i * 64;

        // ---- prefetch tile i+1 (K/V buf flip + 64 new P rows) ----
        if (i < 15) {
            __half* kf = KF + ((i + 1) & 1) * 4608;
            __half* vf = VF + ((i + 1) & 1) * 4608;
            int s0n = s0 + 64;
            for (int x = tid; x < 512; x += 128) {
                int r = x >> 3, c = (x & 7) << 3;
                size_t ksrc = ((size_t)(b * T_ + s0n + r)) * F_ + h * DK_ + c;
                cp16(&kf[r * 72 + c], g_Kf + ksrc);
                size_t vsrc = ((size_t)bh * DK_ + r) * T_ + s0n + c;
                cp16(&vf[r * 72 + c], g_Vf + vsrc);
            }
            int u0 = 192 + 64 * i;
            for (int x = tid; x < 512; x += 128) {
                int rr = x >> 3, c = (x & 7) << 3;
                int un = u0 + rr;
                int slot = un & 255;
                int grow = pbase0 + un; if (grow > P_) grow = P_;
                cp16(&PF[slot * 72 + c], g_Pf + (size_t)grow * F_ + h * DK_ + c);
            }
            asm volatile("cp.async.commit_group;");
        }
        if (tid < 64) MSK[tid] = (mask[b * T_ + s0 + tid] == 0) ? -3.0e38f : 0.f;
        if (i < 15) asm volatile("cp.async.wait_group 1;" ::: "memory");
        else        asm volatile("cp.async.wait_group 0;" ::: "memory");
        __syncthreads();

        const __half* kf = KF + (i & 1) * 4608;
        const __half* vf = VF + (i & 1) * 4608;
        const int off = (64 * i) & 255;

        float sf2[2][8][4];   // S accumulators, preloaded with band+mask

        // ---- per strip: G (banded BD) -> GSw -> band+mask into sf2 ----
#pragma unroll
        for (int ss = 0; ss < 2; ss++) {
            const int st = warp * 2 + ss;
            {
                int prow = 112 - 16 * st + (lane & 7);
                int psel = ((lane >> 3) & 1) << 3;
#pragma unroll
                for (int nt = 0; nt < 10; nt++) {
                    float gA0 = 0.f, gA1 = 0.f, gA2 = 0.f, gA3 = 0.f;
                    float gB0 = 0.f, gB1 = 0.f, gB2 = 0.f, gB3 = 0.f;
                    int prw = (prow + nt * 8 + off) & 255;
#pragma unroll
                    for (int kc = 0; kc < 4; kc += 2) {
                        unsigned p0, p1, p2, p3;
                        ldsm_x2(smem_u32(&PF[prw * 72 + kc * 16 + psel]), p0, p1);
                        ldsm_x2(smem_u32(&PF[prw * 72 + (kc + 1) * 16 + psel]), p2, p3);
                        mma_fp16(gA0, gA1, gA2, gA3,
                                 qvf[ss][kc][0], qvf[ss][kc][1], qvf[ss][kc][2], qvf[ss][kc][3], p0, p1);
                        mma_fp16(gB0, gB1, gB2, gB3,
                                 qvf[ss][kc + 1][0], qvf[ss][kc + 1][1], qvf[ss][kc + 1][2], qvf[ss][kc + 1][3], p2, p3);
                    }
                    int gc = nt * 8 + 2 * tig;
                    GSw[gid * 88 + gc] = gA0 + gB0;
                    GSw[gid * 88 + gc + 1] = gA1 + gB1;
                    GSw[(gid + 8) * 88 + gc] = gA2 + gB2;
                    GSw[(gid + 8) * 88 + gc + 1] = gA3 + gB3;
                }
            }
            __syncwarp();
#pragma unroll
            for (int nt = 0; nt < 8; nt++) {
                int col = nt * 8 + 2 * tig;
                sf2[ss][nt][0] = GSw[gid * 88 + col - gid + 15] + MSK[col];
                sf2[ss][nt][1] = GSw[gid * 88 + col - gid + 16] + MSK[col + 1];
                sf2[ss][nt][2] = GSw[(gid + 8) * 88 + col - gid + 7] + MSK[col];
                sf2[ss][nt][3] = GSw[(gid + 8) * 88 + col - gid + 8] + MSK[col + 1];
            }
            __syncwarp();   // all reads done before next strip rewrites GSw
        }

        // ---- S += qu @ K^T: K fragments loaded ONCE, feed both strips ----
        {
            int krow = lane & 7;
            int ksel = ((lane >> 3) & 1) << 3;
#pragma unroll
            for (int nt = 0; nt < 8; nt++) {
                unsigned k[8];
#pragma unroll
                for (int kc = 0; kc < 4; kc++)
                    ldsm_x2(smem_u32(&kf[(nt * 8 + krow) * 72 + kc * 16 + ksel]),
                            k[2 * kc], k[2 * kc + 1]);
#pragma unroll
                for (int kc = 0; kc < 4; kc++) {
                    mma_fp16(sf2[0][nt][0], sf2[0][nt][1], sf2[0][nt][2], sf2[0][nt][3],
                             quf[0][kc][0], quf[0][kc][1], quf[0][kc][2], quf[0][kc][3],
                             k[2 * kc], k[2 * kc + 1]);
                    mma_fp16(sf2[1][nt][0], sf2[1][nt][1], sf2[1][nt][2], sf2[1][nt][3],
                             quf[1][kc][0], quf[1][kc][1], quf[1][kc][2], quf[1][kc][3],
                             k[2 * kc], k[2 * kc + 1]);
                }
            }
        }

        // ---- online softmax + pack per strip ----
        unsigned af[2][4][4];
#pragma unroll
        for (int ss = 0; ss < 2; ss++) {
            float mx0 = -1e30f, mx1 = -1e30f;
#pragma unroll
            for (int nt = 0; nt < 8; nt++) {
                mx0 = fmaxf(mx0, fmaxf(sf2[ss][nt][0], sf2[ss][nt][1]));
                mx1 = fmaxf(mx1, fmaxf(sf2[ss][nt][2], sf2[ss][nt][3]));
            }
            mx0 = fmaxf(mx0, __shfl_xor_sync(0xffffffffu, mx0, 1));
            mx0 = fmaxf(mx0, __shfl_xor_sync(0xffffffffu, mx0, 2));
            mx1 = fmaxf(mx1, __shfl_xor_sync(0xffffffffu, mx1, 1));
            mx1 = fmaxf(mx1, __shfl_xor_sync(0xffffffffu, mx1, 2));
            float mn0 = fmaxf(mr[ss][0], mx0), mn1 = fmaxf(mr[ss][1], mx1);
            float sc0 = __expf(mr[ss][0] - mn0), sc1 = __expf(mr[ss][1] - mn1);
            float su0 = 0.f, su1 = 0.f;
#pragma unroll
            for (int nt = 0; nt < 8; nt++) {
                sf2[ss][nt][0] = __expf(sf2[ss][nt][0] - mn0);
                sf2[ss][nt][1] = __expf(sf2[ss][nt][1] - mn0);
                sf2[ss][nt][2] = __expf(sf2[ss][nt][2] - mn1);
                sf2[ss][nt][3] = __expf(sf2[ss][nt][3] - mn1);
                su0 += sf2[ss][nt][0] + sf2[ss][nt][1];
                su1 += sf2[ss][nt][2] + sf2[ss][nt][3];
            }
            su0 += __shfl_xor_sync(0xffffffffu, su0, 1);
            su0 += __shfl_xor_sync(0xffffffffu, su0, 2);
            su1 += __shfl_xor_sync(0xffffffffu, su1, 1);
            su1 += __shfl_xor_sync(0xffffffffu, su1, 2);
            lsum[ss][0] = lsum[ss][0] * sc0 + su0;
            lsum[ss][1] = lsum[ss][1] * sc1 + su1;
            mr[ss][0] = mn0; mr[ss][1] = mn1;
#pragma unroll
            for (int nt = 0; nt < 8; nt++) {
                o[ss][nt][0] *= sc0; o[ss][nt][1] *= sc0;
                o[ss][nt][2] *= sc1; o[ss][nt][3] *= sc1;
            }
#pragma unroll
            for (int kc = 0; kc < 4; kc++) {
                pack_f16(sf2[ss][2 * kc][0], sf2[ss][2 * kc][1], af[ss][kc][0]);
                pack_f16(sf2[ss][2 * kc][2], sf2[ss][2 * kc][3], af[ss][kc][1]);
                pack_f16(sf2[ss][2 * kc + 1][0], sf2[ss][2 * kc + 1][1], af[ss][kc][2]);
                pack_f16(sf2[ss][2 * kc + 1][2], sf2[ss][2 * kc + 1][3], af[ss][kc][3]);
            }
        }

        // ---- O += P @ V: V fragments loaded ONCE, feed both strips ----
        {
            int vrow = lane & 7;
            int vsel = ((lane >> 3) & 1) << 3;
#pragma unroll
            for (int kc = 0; kc < 4; kc++) {
#pragma unroll
                for (int nt = 0; nt < 8; nt++) {
                    unsigned v0, v1;
                    ldsm_x2(smem_u32(&vf[(nt * 8 + vrow) * 72 + kc * 16 + vsel]), v0, v1);
                    mma_fp16(o[0][nt][0], o[0][nt][1], o[0][nt][2], o[0][nt][3],
                             af[0][kc][0], af[0][kc][1], af[0][kc][2], af[0][kc][3], v0, v1);
                    mma_fp16(o[1][nt][0], o[1][nt][1], o[1][nt][2], o[1][nt][3],
                             af[1][kc][0], af[1][kc][1], af[1][kc][2], af[1][kc][3], v0, v1);
                }
            }
        }
        __syncthreads();
    }

    // ---- epilogue: write ctx fp16 (both strips) ----
#pragma unroll
    for (int ss = 0; ss < 2; ss++) {
        float inv0 = (lsum[ss][0] > 0.f) ? 1.f / lsum[ss][0] : 0.f;
        float inv1 = (lsum[ss][1] > 0.f) ? 1.f / lsum[ss][1] : 0.f;
        int row0 = t0 + (warp * 2 + ss) * 16 + gid;
#pragma unroll
        for (int nt = 0; nt < 8; nt++) {
            int colg = h * DK_ + nt * 8 + 2 * tig;
            __half2 w0 = __floats2half2_rn(o[ss][nt][0] * inv0, o[ss][nt][1] * inv0);
            *(__half2*)&g_Cf[((size_t)(b * T_ + row0)) * F_ + colg] = w0;
            __half2 w1 = __floats2half2_rn(o[ss][nt][2] * inv1, o[ss][nt][3] * inv1);
            *(__half2*)&g_Cf[((size_t)(b * T_ + row0 + 8)) * F_ + colg] = w1;
        }
    }
}

// =====================================================================
extern "C" void kernel_launch(void* const* d_in, const int* in_sizes, int n_in,
                              void* d_out, int out_size)
{
    const float* query   = (const float*)d_in[0];
    const float* key_in  = (const float*)d_in[1];
    const float* value   = (const float*)d_in[2];
    const float* pos_emb = (const float*)d_in[3];
    const int*   mask    = (const int*)d_in[4];
    const float* Wq = (const float*)d_in[5];
    const float* bq = (const float*)d_in[6];
    const float* Wk = (const float*)d_in[7];
    const float* bk = (const float*)d_in[8];
    const float* Wv = (const float*)d_in[9];
    const float* bv = (const float*)d_in[10];
    const float* Wo = (const float*)d_in[11];
    const float* bo = (const float*)d_in[12];
    const float* Wp = (const float*)d_in[13];
    const float* pu = (const float*)d_in[14];
    const float* pv = (const float*)d_in[15];
    float* out = (float*)d_out;

    __half *Xq, *Xk, *Xv, *Xp, *Wqf, *Wkf, *Wvf, *Wpf, *Wof;
    __half *Qfp, *Kfp, *Vfp, *Pfp, *Cfp;
    cudaGetSymbolAddress((void**)&Xq,  g_Xq);
    cudaGetSymbolAddress((void**)&Xk,  g_Xk);
    cudaGetSymbolAddress((void**)&Xv,  g_Xv);
    cudaGetSymbolAddress((void**)&Xp,  g_Xp);
    cudaGetSymbolAddress((void**)&Wqf, g_Wq);
    cudaGetSymbolAddress((void**)&Wkf, g_Wk);
    cudaGetSymbolAddress((void**)&Wvf, g_Wv);
    cudaGetSymbolAddress((void**)&Wpf, g_Wp);
    cudaGetSymbolAddress((void**)&Wof, g_Wo);
    cudaGetSymbolAddress((void**)&Qfp, g_Qf);
    cudaGetSymbolAddress((void**)&Kfp, g_Kf);
    cudaGetSymbolAddress((void**)&Vfp, g_Vf);
    cudaGetSymbolAddress((void**)&Pfp, g_Pf);
    cudaGetSymbolAddress((void**)&Cfp, g_Cf);

    cudaFuncSetAttribute(flash_kernel, cudaFuncAttributeMaxDynamicSharedMemorySize, FL_SMEM);
    cudaFuncSetAttribute(gemm_f16, cudaFuncAttributeMaxDynamicSharedMemorySize, G16_SMEM);

    // ---- prepass: fp32 -> fp16 for all GEMM operands ----
    const int NBT = B_ * T_ * F_ / 4;
    const int NP  = P_ * F_ / 4;
    const int NW  = F_ * F_ / 4;
    CvtJobs cj;
    cj.j[0] = { query,   Xq,  NBT };
    cj.j[1] = { key_in,  Xk,  NBT };
    cj.j[2] = { value,   Xv,  NBT };
    cj.j[3] = { pos_emb, Xp,  NP  };
    cj.j[4] = { Wq, Wqf, NW };
    cj.j[5] = { Wk, Wkf, NW };
    cj.j[6] = { Wv, Wvf, NW };
    cj.j[7] = { Wp, Wpf, NW };
    cj.j[8] = { Wo, Wof, NW };
    cvt_f16<<<dim3(256, 9), 256>>>(cj);

    // ---- all 4 input projections in ONE launch (fp16 x1, 3-stage) ----
    GemmJobs pj;
    pj.j[0] = { Xq, Wqf, bq,      nullptr, Qfp, B_ * T_, 1 };
    pj.j[1] = { Xk, Wkf, bk,      nullptr, Kfp, B_ * T_, 1 };
    pj.j[2] = { Xv, Wvf, bv,      nullptr, Vfp, B_ * T_, 2 };
    pj.j[3] = { Xp, Wpf, nullptr, nullptr, Pfp, P_,      1 };
    gemm_f16<<<dim3(4, 64, 4), 256, G16_SMEM>>>(pj);

    // fused attention (fp16, 2 strips/warp, shared K+V loads, 2 CTAs/SM)
    flash_kernel<<<dim3(8, B_ * H_), 128, FL_SMEM>>>(pu, pv, mask);

    // output projection (fp16 x1, fp32 out, 3-stage)
    GemmJobs oj;
    oj.j[0] = { Cfp, Wof, bo, out, nullptr, B_ * T_, 0 };
    oj.j[1] = oj.j[0]; oj.j[2] = oj.j[0]; oj.j[3] = oj.j[0];
    gemm_f16<<<dim3(4, 64, 1), 256, G16_SMEM>>>(oj);
}